// round 14
// baseline (speedup 1.0000x reference)
#include <cuda_runtime.h>
#include <cuda_bf16.h>
#include <math.h>
#include <stdint.h>

#define BATCH 16
#define DB    32                 // batched decoders: train(0..15) + test(16..31)
#define SEQ   1024
#define DM    512
#define KD    128
#define TEMP_F 30.0f
#define EPB   (SEQ*DM)
#define PS    2048               // part-section stride (32 batches x 64 tiles)
#define NORM_SCALE_F 0.011048543456039806f   // sqrt(1/(512*16))

typedef __nv_bfloat16 bf16;

// ---------------- scratch (static device memory; allocation-free) ----------
__device__ __align__(16) float g_Sc  [DB*SEQ*SEQ];                           // fp32 scores
__device__ __align__(16) bf16 g_Xh  [DB*SEQ*DM], g_Xl  [DB*SEQ*DM];          // x   [b][S][D]
__device__ __align__(16) bf16 g_Xth [DB*SEQ*DM], g_Xtl [DB*SEQ*DM];          // x^T [b][D][S]
__device__ __align__(16) bf16 g_V2th[BATCH*SEQ*DM], g_V2tl[BATCH*SEQ*DM];    // (mem*lbl)^T
__device__ __align__(16) bf16 g_Bh  [DB*SEQ*DM], g_Bl  [DB*SEQ*DM];          // residual sums
__device__ __align__(16) bf16 g_Wh  [DB*SEQ*KD], g_Wl  [DB*SEQ*KD];
__device__ __align__(16) bf16 g_Wkmh[BATCH*SEQ*KD], g_Wkml[BATCH*SEQ*KD];
__device__ __align__(16) bf16 g_Sch [DB*SEQ*SEQ], g_Scl[DB*SEQ*SEQ];
__device__ __align__(16) bf16 g_WKth[2*KD*DM], g_WKtl[2*KD*DM];              // WK^T [K][D]
__device__ float g_mask[DB*SEQ];
__device__ float g_part[3*PS];

__device__ __forceinline__ void bsplit(float x, bf16& h, bf16& l)
{
    bf16 hh = __float2bfloat16(x);
    h = hh;
    l = __float2bfloat16(x - __bfloat162float(hh));
}
__device__ __forceinline__ float upk0(uint32_t u){ return __bfloat162float(((__nv_bfloat162*)&u)->x); }
__device__ __forceinline__ float upk1(uint32_t u){ return __bfloat162float(((__nv_bfloat162*)&u)->y); }
__device__ __forceinline__ uint32_t pack2(bf16 a, bf16 b){
    __nv_bfloat162 t; t.x = a; t.y = b; return *(uint32_t*)&t;
}

// ====================== pure-bf16 3-pass tensor-core GEMM ==================
// C = (Ah+Al) @ (Bh+Bl)^T (drop Al*Bl).  A:[M,K], B:[N,K], both row-major.
// CTA tile 64x128 (2 CTAs/SM), BK=32, 2-stage cp.async, 8 warps (2m x 4n),
// warp tile 32x32, mma m16n8k16. B batch index = blockIdx.z & zband.
// EPI: 0 = fp32 C store; 1 = bias + row-L2 + bf16 split (proj, N=128, grid.x=1)
//      2 = +residual x, emit splits, sumsq partials (self AV)
//      3 = +residual x, emit splits, Sbb/Saa/Sab partials (cross t3)

__device__ __forceinline__ void mma_bf16(float* c, const uint32_t* a, const uint32_t* b)
{
    asm volatile(
        "mma.sync.aligned.m16n8k16.row.col.f32.bf16.bf16.f32 "
        "{%0,%1,%2,%3},{%4,%5,%6,%7},{%8,%9},{%0,%1,%2,%3};"
        : "+f"(c[0]), "+f"(c[1]), "+f"(c[2]), "+f"(c[3])
        : "r"(a[0]), "r"(a[1]), "r"(a[2]), "r"(a[3]), "r"(b[0]), "r"(b[1]));
}

#define CP_ASYNC16(dst_u32, src_ptr) \
    asm volatile("cp.async.cg.shared.global [%0], [%1], 16;\n" :: "r"(dst_u32), "l"(src_ptr))
#define CP_COMMIT()  asm volatile("cp.async.commit_group;\n" ::)
#define CP_WAIT_1()  asm volatile("cp.async.wait_group 1;\n" ::)
#define CP_WAIT_0()  asm volatile("cp.async.wait_group 0;\n" ::)

// stage layout (words): Ah[64*20] Al[64*20] Bh[128*20] Bl[128*20]
#define ATILE_W  1280
#define BTILE_W  2560
#define STAGE_W  (2*ATILE_W + 2*BTILE_W)     // 7680 words
#define GEMM_SMEM_BYTES (2*STAGE_W*4)        // 61440 B -> 2 CTAs/SM

template<int EPI>
__global__ void __launch_bounds__(256, 2)
k_gemm(const bf16* __restrict__ Ahg, const bf16* __restrict__ Alg,
       const bf16* __restrict__ Bhg, const bf16* __restrict__ Blg,
       float* __restrict__ Cg, bf16* __restrict__ OH, bf16* __restrict__ OL,
       const bf16* __restrict__ RXh, const bf16* __restrict__ RXl,
       const float* __restrict__ bm_aux,   // EPI1: bias[N]; EPI3: mask[b*SEQ]
       float* __restrict__ part, int zband,
       int M, int N, int K, size_t sA, size_t sB, size_t sC)
{
    extern __shared__ uint32_t sm[];
    const bf16* Ah = Ahg + (size_t)blockIdx.z * sA;
    const bf16* Al = Alg + (size_t)blockIdx.z * sA;
    const bf16* Bh = Bhg + (size_t)(blockIdx.z & zband) * sB;
    const bf16* Bl = Blg + (size_t)(blockIdx.z & zband) * sB;

    const int bm = blockIdx.y * 64;
    const int bn = blockIdx.x * 128;
    const int tid  = threadIdx.x;
    const int lane = tid & 31;
    const int warp = tid >> 5;
    const int wm = (warp & 1) * 32;    // 2 m-warps
    const int wn = (warp >> 1) * 32;   // 4 n-warps
    const int qid = lane >> 2;
    const int tig = lane & 3;

    const uint32_t sbase = (uint32_t)__cvta_generic_to_shared(sm);

    auto load_stage = [&](int st, int k0) {
        uint32_t stb = sbase + st * (STAGE_W * 4);
        {   // A tiles: 64 rows, 1 chunk/thread/tile
            int rr = tid >> 2, cc = tid & 3;
            uint32_t woff = (rr * 20 + cc * 4) * 4;
            size_t ga = (size_t)(bm + rr) * K + k0 + cc * 8;
            CP_ASYNC16(stb + woff, Ah + ga);
            CP_ASYNC16(stb + ATILE_W*4 + woff, Al + ga);
        }
        #pragma unroll
        for (int h = 0; h < 2; h++) {   // B tiles: 128 rows, 2 chunks/thread/tile
            int idx = tid + h * 256;
            int rr = idx >> 2, cc = idx & 3;
            uint32_t woff = (rr * 20 + cc * 4) * 4;
            size_t gb = (size_t)(bn + rr) * K + k0 + cc * 8;
            CP_ASYNC16(stb + 2*ATILE_W*4 + woff, Bh + gb);
            CP_ASYNC16(stb + (2*ATILE_W + BTILE_W)*4 + woff, Bl + gb);
        }
        CP_COMMIT();
    };

    float acc[2][4][4] = {};
    const int nIter = K >> 5;
    load_stage(0, 0);

    for (int it = 0; it < nIter; ++it) {
        if (it + 1 < nIter) { load_stage((it + 1) & 1, (it + 1) * 32); CP_WAIT_1(); }
        else                { CP_WAIT_0(); }
        __syncthreads();

        const uint32_t* As_h = sm + (it & 1) * STAGE_W;
        const uint32_t* As_l = As_h + ATILE_W;
        const uint32_t* Bs_h = As_h + 2*ATILE_W;
        const uint32_t* Bs_l = Bs_h + BTILE_W;

        #pragma unroll
        for (int ks = 0; ks < 2; ks++) {
            const int kw = ks * 8 + tig;
            uint32_t ah[2][4], bh[4][2], bl[4][2];
            #pragma unroll
            for (int mi = 0; mi < 2; mi++) {
                int b0 = (wm + mi*16 + qid) * 20 + kw;
                ah[mi][0] = As_h[b0];       ah[mi][1] = As_h[b0 + 160];
                ah[mi][2] = As_h[b0 + 4];   ah[mi][3] = As_h[b0 + 164];
            }
            #pragma unroll
            for (int ni = 0; ni < 4; ni++) {
                int b0 = (wn + ni*8 + qid) * 20 + kw;
                bh[ni][0] = Bs_h[b0];  bh[ni][1] = Bs_h[b0 + 4];
                bl[ni][0] = Bs_l[b0];  bl[ni][1] = Bs_l[b0 + 4];
            }
            #pragma unroll
            for (int mi = 0; mi < 2; mi++)
                #pragma unroll
                for (int ni = 0; ni < 4; ni++)
                    mma_bf16(acc[mi][ni], ah[mi], bh[ni]);
            #pragma unroll
            for (int mi = 0; mi < 2; mi++)
                #pragma unroll
                for (int ni = 0; ni < 4; ni++)
                    mma_bf16(acc[mi][ni], ah[mi], bl[ni]);
            uint32_t al[2][4];
            #pragma unroll
            for (int mi = 0; mi < 2; mi++) {
                int b0 = (wm + mi*16 + qid) * 20 + kw;
                al[mi][0] = As_l[b0];       al[mi][1] = As_l[b0 + 160];
                al[mi][2] = As_l[b0 + 4];   al[mi][3] = As_l[b0 + 164];
            }
            #pragma unroll
            for (int mi = 0; mi < 2; mi++)
                #pragma unroll
                for (int ni = 0; ni < 4; ni++)
                    mma_bf16(acc[mi][ni], al[mi], bh[ni]);
        }
        __syncthreads();
    }

    const size_t zC = (size_t)blockIdx.z * sC;

    if (EPI == 0) {
        float* C = Cg + zC;
        #pragma unroll
        for (int mi = 0; mi < 2; mi++)
            #pragma unroll
            for (int ni = 0; ni < 4; ni++) {
                const int r = bm + wm + mi * 16 + qid;
                const int c = bn + wn + ni * 8 + 2 * tig;
                *(float2*)&C[(size_t)r * N + c]       = make_float2(acc[mi][ni][0], acc[mi][ni][1]);
                *(float2*)&C[(size_t)(r + 8) * N + c] = make_float2(acc[mi][ni][2], acc[mi][ni][3]);
            }
    }
    else if (EPI == 1) {
        float* srow = (float*)sm;   // [64][4]
        float rs[2][2];
        #pragma unroll
        for (int mi = 0; mi < 2; mi++) { rs[mi][0] = 0.f; rs[mi][1] = 0.f; }
        #pragma unroll
        for (int mi = 0; mi < 2; mi++)
            #pragma unroll
            for (int ni = 0; ni < 4; ni++) {
                const int c = bn + wn + ni * 8 + 2 * tig;
                float b0 = bm_aux[c], b1 = bm_aux[c + 1];
                acc[mi][ni][0] += b0; acc[mi][ni][1] += b1;
                acc[mi][ni][2] += b0; acc[mi][ni][3] += b1;
                rs[mi][0] += acc[mi][ni][0]*acc[mi][ni][0] + acc[mi][ni][1]*acc[mi][ni][1];
                rs[mi][1] += acc[mi][ni][2]*acc[mi][ni][2] + acc[mi][ni][3]*acc[mi][ni][3];
            }
        #pragma unroll
        for (int mi = 0; mi < 2; mi++)
            #pragma unroll
            for (int h = 0; h < 2; h++) {
                float v = rs[mi][h];
                v += __shfl_xor_sync(0xffffffffu, v, 1);
                v += __shfl_xor_sync(0xffffffffu, v, 2);
                rs[mi][h] = v;
            }
        if (tig == 0)
            #pragma unroll
            for (int mi = 0; mi < 2; mi++)
                #pragma unroll
                for (int h = 0; h < 2; h++)
                    srow[(wm + mi*16 + qid + h*8) * 4 + (wn >> 5)] = rs[mi][h];
        __syncthreads();
        #pragma unroll
        for (int mi = 0; mi < 2; mi++)
            #pragma unroll
            for (int h = 0; h < 2; h++) {
                int rl = wm + mi*16 + qid + h*8;
                float tot = srow[rl*4] + srow[rl*4+1] + srow[rl*4+2] + srow[rl*4+3];
                float inv = 1.f / fmaxf(sqrtf(tot), 1e-12f);
                #pragma unroll
                for (int ni = 0; ni < 4; ni++) {
                    const int c = bn + wn + ni * 8 + 2 * tig;
                    size_t i = zC + (size_t)(bm + rl) * N + c;
                    bf16 h0,l0,h1,l1;
                    bsplit(acc[mi][ni][2*h]   * inv, h0, l0);
                    bsplit(acc[mi][ni][2*h+1] * inv, h1, l1);
                    *(uint32_t*)(OH + i) = pack2(h0, h1);
                    *(uint32_t*)(OL + i) = pack2(l0, l1);
                }
            }
    }
    else {  // EPI 2 / 3: residual add + split emit + partial sums
        const bf16* Xh = RXh + zC;
        const bf16* Xl = RXl + zC;
        float saa = 0.f, sab = 0.f, sbb = 0.f;
        #pragma unroll
        for (int mi = 0; mi < 2; mi++) {
            const int r0 = bm + wm + mi * 16 + qid;
            float mk0 = 0.f, mk1 = 0.f;
            if (EPI == 3) {
                mk0 = bm_aux[blockIdx.z * SEQ + r0];
                mk1 = bm_aux[blockIdx.z * SEQ + r0 + 8];
            }
            #pragma unroll
            for (int ni = 0; ni < 4; ni++) {
                const int c = bn + wn + ni * 8 + 2 * tig;
                size_t i0 = (size_t)r0 * N + c;
                size_t i1 = i0 + (size_t)8 * N;
                uint32_t xh0 = *(const uint32_t*)(Xh + i0), xl0 = *(const uint32_t*)(Xl + i0);
                uint32_t xh1 = *(const uint32_t*)(Xh + i1), xl1 = *(const uint32_t*)(Xl + i1);
                float x00 = upk0(xh0)+upk0(xl0), x01 = upk1(xh0)+upk1(xl0);
                float x10 = upk0(xh1)+upk0(xl1), x11 = upk1(xh1)+upk1(xl1);
                float v00 = acc[mi][ni][0] + x00, v01 = acc[mi][ni][1] + x01;
                float v10 = acc[mi][ni][2] + x10, v11 = acc[mi][ni][3] + x11;
                sbb += v00*v00 + v01*v01 + v10*v10 + v11*v11;
                if (EPI == 3) {
                    float a00 = x00*mk0, a01 = x01*mk0, a10 = x10*mk1, a11 = x11*mk1;
                    saa += a00*a00 + a01*a01 + a10*a10 + a11*a11;
                    sab += a00*v00 + a01*v01 + a10*v10 + a11*v11;
                }
                bf16 h0,l0,h1,l1;
                bsplit(v00, h0, l0); bsplit(v01, h1, l1);
                *(uint32_t*)(OH + zC + i0) = pack2(h0, h1);
                *(uint32_t*)(OL + zC + i0) = pack2(l0, l1);
                bsplit(v10, h0, l0); bsplit(v11, h1, l1);
                *(uint32_t*)(OH + zC + i1) = pack2(h0, h1);
                *(uint32_t*)(OL + zC + i1) = pack2(l0, l1);
            }
        }
        float* red = (float*)sm;   // [3][8]
        #pragma unroll
        for (int o = 16; o; o >>= 1) {
            sbb += __shfl_xor_sync(0xffffffffu, sbb, o);
            if (EPI == 3) {
                saa += __shfl_xor_sync(0xffffffffu, saa, o);
                sab += __shfl_xor_sync(0xffffffffu, sab, o);
            }
        }
        if (lane == 0) {
            red[warp] = sbb;
            if (EPI == 3) { red[8 + warp] = saa; red[16 + warp] = sab; }
        }
        __syncthreads();
        if (tid == 0) {
            const int tileId = blockIdx.y * gridDim.x + blockIdx.x;   // 0..63
            float tb = 0.f; for (int i = 0; i < 8; i++) tb += red[i];
            part[blockIdx.z * 64 + tileId] = tb;
            if (EPI == 3) {
                float ta = 0.f, tc = 0.f;
                for (int i = 0; i < 8; i++) { ta += red[8+i]; tc += red[16+i]; }
                part[PS   + blockIdx.z * 64 + tileId] = ta;   // Saa
                part[2*PS + blockIdx.z * 64 + tileId] = tc;   // Sab
            }
        }
    }
}

// ---------------- weight transpose + split: WK[D][K] -> WKt[K][D] ----------
__global__ void k_split_wt(const float* __restrict__ Wk, bf16* __restrict__ th,
                           bf16* __restrict__ tl)
{
    __shared__ float tile[32][33];
    int k0 = blockIdx.x * 32, d0 = blockIdx.y * 32;
    for (int r = threadIdx.y; r < 32; r += 8)
        tile[r][threadIdx.x] = Wk[(size_t)(d0 + r) * KD + k0 + threadIdx.x];
    __syncthreads();
    for (int r = threadIdx.y; r < 32; r += 8) {
        size_t idx = (size_t)(k0 + r) * DM + d0 + threadIdx.x;
        bsplit(tile[threadIdx.x][r], th[idx], tl[idx]);
    }
}

// ---------------- input: [b,D,S] fp32 -> X splits [b,S,D] + Xt [b,D,S] -----
__global__ void k_trans_in(const float* __restrict__ in,
                           bf16* __restrict__ Xh, bf16* __restrict__ Xl,
                           bf16* __restrict__ Xth, bf16* __restrict__ Xtl)
{
    __shared__ bf16 tH[32][33], tL[32][33];
    int b = blockIdx.z;
    int d0 = blockIdx.y * 32, s0 = blockIdx.x * 32;
    for (int r = threadIdx.y; r < 32; r += 8) {
        size_t ti = ((size_t)b*DM + d0 + r) * SEQ + s0 + threadIdx.x;
        bf16 h, l;
        bsplit(in[ti], h, l);
        Xth[ti] = h; Xtl[ti] = l;     // input is already [D][S]
        tH[r][threadIdx.x] = h; tL[r][threadIdx.x] = l;
    }
    __syncthreads();
    for (int r = threadIdx.y; r < 32; r += 8) {
        size_t idx = ((size_t)b*SEQ + s0 + r) * DM + d0 + threadIdx.x;
        Xh[idx] = tH[threadIdx.x][r];
        Xl[idx] = tL[threadIdx.x][r];
    }
}

// ---------------- output transpose: splits [b,S,D] -> fp32 [b,D,S] ---------
__global__ void k_trans_out(const bf16* __restrict__ Xh, const bf16* __restrict__ Xl,
                            float* __restrict__ out)
{
    __shared__ float tile[32][33];
    int b = blockIdx.z;
    int d0 = blockIdx.y * 32, s0 = blockIdx.x * 32;
    for (int r = threadIdx.y; r < 32; r += 8) {
        size_t idx = ((size_t)b*SEQ + s0 + r) * DM + d0 + threadIdx.x;
        tile[r][threadIdx.x] = __bfloat162float(Xh[idx]) + __bfloat162float(Xl[idx]);
    }
    __syncthreads();
    for (int r = threadIdx.y; r < 32; r += 8)
        out[((size_t)b*DM + d0 + r) * SEQ + s0 + threadIdx.x] = tile[threadIdx.x][r];
}

// ---------------- V2^T: (mem * label) transposed + split --------------------
__global__ void k_v2t(const bf16* __restrict__ Mh, const bf16* __restrict__ Ml,
                      const float* __restrict__ lbl,
                      bf16* __restrict__ th, bf16* __restrict__ tl)
{
    __shared__ float tile[32][33];
    int b = blockIdx.z;
    int s0 = blockIdx.x * 32, d0 = blockIdx.y * 32;
    for (int r = threadIdx.y; r < 32; r += 8) {
        size_t idx = ((size_t)b*SEQ + s0 + r) * DM + d0 + threadIdx.x;
        float v = __bfloat162float(Mh[idx]) + __bfloat162float(Ml[idx]);
        tile[r][threadIdx.x] = v * lbl[b*SEQ + s0 + r];
    }
    __syncthreads();
    for (int r = threadIdx.y; r < 32; r += 8) {
        size_t idx = ((size_t)b*DM + d0 + r) * SEQ + s0 + threadIdx.x;
        bsplit(tile[threadIdx.x][r], th[idx], tl[idx]);
    }
}

// ---------------- softmax (optionally fused mask GEMV) ----------------------
template<bool MASK>
__global__ void k_softmax(const float* __restrict__ Sc, bf16* __restrict__ Ph,
                          bf16* __restrict__ Pl, float* __restrict__ mask,
                          const float* __restrict__ lbl, int lband)
{
    __shared__ float sh1[8], sh2[8];
    int b = blockIdx.y, q = blockIdx.x, t = threadIdx.x;   // 256 threads
    size_t ro = ((size_t)b*SEQ + q) * SEQ;
    float4 v = reinterpret_cast<const float4*>(Sc + ro)[t];
    v.x *= TEMP_F; v.y *= TEMP_F; v.z *= TEMP_F; v.w *= TEMP_F;
    float m = fmaxf(fmaxf(v.x, v.y), fmaxf(v.z, v.w));
    #pragma unroll
    for (int o = 16; o; o >>= 1) m = fmaxf(m, __shfl_xor_sync(0xffffffffu, m, o));
    if ((t & 31) == 0) sh1[t >> 5] = m;
    __syncthreads();
    m = fmaxf(fmaxf(fmaxf(sh1[0], sh1[1]), fmaxf(sh1[2], sh1[3])),
              fmaxf(fmaxf(sh1[4], sh1[5]), fmaxf(sh1[6], sh1[7])));
    v.x = __expf(v.x - m); v.y = __expf(v.y - m);
    v.z = __expf(v.z - m); v.w = __expf(v.w - m);
    float sum = v.x + v.y + v.z + v.w;
    #pragma unroll
    for (int o = 16; o; o >>= 1) sum += __shfl_xor_sync(0xffffffffu, sum, o);
    if ((t & 31) == 0) sh2[t >> 5] = sum;
    __syncthreads();
    sum = sh2[0]+sh2[1]+sh2[2]+sh2[3]+sh2[4]+sh2[5]+sh2[6]+sh2[7];
    float inv = 1.f / sum;
    float p0 = v.x*inv, p1 = v.y*inv, p2 = v.z*inv, p3 = v.w*inv;
    bf16 h0,l0,h1,l1,h2,l2,h3,l3;
    bsplit(p0,h0,l0); bsplit(p1,h1,l1); bsplit(p2,h2,l2); bsplit(p3,h3,l3);
    uint2 uh; uh.x = pack2(h0,h1); uh.y = pack2(h2,h3);
    uint2 ul; ul.x = pack2(l0,l1); ul.y = pack2(l2,l3);
    *(uint2*)(Ph + ro + 4*t) = uh;
    *(uint2*)(Pl + ro + 4*t) = ul;
    if (MASK) {
        float4 L = reinterpret_cast<const float4*>(lbl + (size_t)(b & lband)*SEQ)[t];
        float s = p0*L.x + p1*L.y + p2*L.z + p3*L.w;
        #pragma unroll
        for (int o = 16; o; o >>= 1) s += __shfl_xor_sync(0xffffffffu, s, o);
        __syncthreads();
        if ((t & 31) == 0) sh1[t >> 5] = s;
        __syncthreads();
        if (t == 0)
            mask[b*SEQ + q] = sh1[0]+sh1[1]+sh1[2]+sh1[3]+sh1[4]+sh1[5]+sh1[6]+sh1[7];
    }
}

// ---------------- self-norm finalize: linear (no Xt emit) -------------------
__global__ void k_scale_emit8(const bf16* __restrict__ Bh, const bf16* __restrict__ Bl,
                              const float* __restrict__ part,
                              bf16* __restrict__ Xh, bf16* __restrict__ Xl)
{
    int b = blockIdx.y;
    float s = 0.f;
    #pragma unroll
    for (int i = 0; i < 64; i++) s += part[b*64 + i];
    float f = NORM_SCALE_F * sqrtf(524288.f / (s + 1e-5f));
    size_t i = (size_t)b*EPB + (size_t)blockIdx.x*2048 + threadIdx.x*8;
    uint4 uh = *(const uint4*)(Bh + i);
    uint4 ul = *(const uint4*)(Bl + i);
    uint32_t oh[4], ol[4];
    const uint32_t* ph = (const uint32_t*)&uh;
    const uint32_t* pl = (const uint32_t*)&ul;
    #pragma unroll
    for (int j = 0; j < 4; j++) {
        float v0 = (upk0(ph[j]) + upk0(pl[j])) * f;
        float v1 = (upk1(ph[j]) + upk1(pl[j])) * f;
        bf16 h0,l0,h1,l1;
        bsplit(v0,h0,l0); bsplit(v1,h1,l1);
        oh[j] = pack2(h0,h1); ol[j] = pack2(l0,l1);
    }
    *(uint4*)(Xh + i) = *(uint4*)oh;
    *(uint4*)(Xl + i) = *(uint4*)ol;
}

// ---------------- self-norm finalize: tiled, emits Xt too -------------------
__global__ void k_scale_emit_tr(const bf16* __restrict__ Bh, const bf16* __restrict__ Bl,
                                const float* __restrict__ part,
                                bf16* __restrict__ Xh, bf16* __restrict__ Xl,
                                bf16* __restrict__ Xth, bf16* __restrict__ Xtl)
{
    __shared__ bf16 tH[32][33], tL[32][33];
    int b = blockIdx.z;
    float s = 0.f;
    #pragma unroll
    for (int i = 0; i < 64; i++) s += part[b*64 + i];
    float f = NORM_SCALE_F * sqrtf(524288.f / (s + 1e-5f));
    int s0 = blockIdx.x * 32, d0 = blockIdx.y * 32;
    for (int r = threadIdx.y; r < 32; r += 8) {
        size_t idx = ((size_t)b*SEQ + s0 + r) * DM + d0 + threadIdx.x;
        float v = (__bfloat162float(Bh[idx]) + __bfloat162float(Bl[idx])) * f;
        bf16 h, l; bsplit(v, h, l);
        Xh[idx] = h; Xl[idx] = l;
        tH[r][threadIdx.x] = h; tL[r][threadIdx.x] = l;
    }
    __syncthreads();
    for (int r = threadIdx.y; r < 32; r += 8) {
        size_t idx = ((size_t)b*DM + d0 + r) * SEQ + s0 + threadIdx.x;
        Xth[idx] = tH[threadIdx.x][r];
        Xtl[idx] = tL[threadIdx.x][r];
    }
}

// ---------------- cross finalize: tiled, factors inline, emits Xt -----------
__global__ void k_cross_final_tr(bf16* __restrict__ Xh, bf16* __restrict__ Xl,
                                 const bf16* __restrict__ Bh, const bf16* __restrict__ Bl,
                                 const float* __restrict__ mask,
                                 const float* __restrict__ part,
                                 bf16* __restrict__ Xth, bf16* __restrict__ Xtl)
{
    __shared__ bf16 tH[32][33], tL[32][33];
    int b = blockIdx.z;
    float sbb = 0.f, saa = 0.f, sab = 0.f;
    #pragma unroll
    for (int i = 0; i < 64; i++) {
        sbb += part[b*64 + i];
        saa += part[PS   + b*64 + i];
        sab += part[2*PS + b*64 + i];
    }
    float f2 = NORM_SCALE_F * sqrtf(524288.f / (saa + 1e-5f));
    float f4 = NORM_SCALE_F * sqrtf(524288.f / (sbb + 1e-5f));
    float sf = f2*f2*saa + 2.f*f2*f4*sab + f4*f4*sbb;
    float F  = NORM_SCALE_F * sqrtf(524288.f / (sf + 1e-5f));
    float ca = F * f2, cb = F * f4;

    int s0 = blockIdx.x * 32, d0 = blockIdx.y * 32;
    for (int r = threadIdx.y; r < 32; r += 8) {
        size_t idx = ((size_t)b*SEQ + s0 + r) * DM + d0 + threadIdx.x;
        float camk = ca * mask[b*SEQ + s0 + r];
        float x = __bfloat162float(Xh[idx]) + __bfloat162float(Xl[idx]);
        float bv = __bfloat162float(Bh[idx]) + __bfloat162float(Bl[idx]);
        float v = camk * x + cb * bv;
        bf16 h, l; bsplit(v, h, l);
        Xh[idx] = h; Xl[idx] = l;
        tH[r][threadIdx.x] = h; tL[r][threadIdx.x] = l;
    }
    __syncthreads();
    for (int r = threadIdx.y; r < 32; r += 8) {
        size_t idx = ((size_t)b*DM + d0 + r) * SEQ + s0 + threadIdx.x;
        Xth[idx] = tH[threadIdx.x][r];
        Xtl[idx] = tL[threadIdx.x][r];
    }
}

// =================== host-side orchestration ===============================
namespace {

struct Ptrs {
    float *Sc, *mask, *part;
    bf16 *Xh, *Xl, *Xth, *Xtl, *V2th, *V2tl, *Bh, *Bl,
         *Wh, *Wl, *Wkmh, *Wkml, *Sch, *Scl, *WKth, *WKtl;
};

inline void proj(int wsel, const float* bK, bf16* outH, bf16* outL, int nb, const Ptrs& p)
{
    k_gemm<1><<<dim3(1, 16, nb), 256, GEMM_SMEM_BYTES>>>(
        p.Xh, p.Xl, p.WKth + (size_t)wsel*KD*DM, p.WKtl + (size_t)wsel*KD*DM,
        nullptr, outH, outL, nullptr, nullptr, bK, nullptr, 0,
        SEQ, KD, DM, (size_t)SEQ*DM, 0, (size_t)SEQ*KD);
}

// Xth/Xtl must already hold the transpose of the current X (producer-emitted)
inline void self_block(const float* bKs, bool emitT, int nb, const Ptrs& p)
{
    proj(0, bKs, p.Wh, p.Wl, nb, p);
    k_gemm<0><<<dim3(8, 16, nb), 256, GEMM_SMEM_BYTES>>>(    // scores (self: B==A)
        p.Wh, p.Wl, p.Wh, p.Wl, p.Sc, nullptr, nullptr, nullptr, nullptr,
        nullptr, nullptr, 31, SEQ, SEQ, KD, (size_t)SEQ*KD, (size_t)SEQ*KD, (size_t)SEQ*SEQ);
    k_softmax<false><<<dim3(SEQ, nb), 256>>>(p.Sc, p.Sch, p.Scl, nullptr, nullptr, 0);
    k_gemm<2><<<dim3(4, 16, nb), 256, GEMM_SMEM_BYTES>>>(
        p.Sch, p.Scl, p.Xth, p.Xtl, nullptr, p.Bh, p.Bl, p.Xh, p.Xl,
        nullptr, p.part, 31, SEQ, DM, SEQ, (size_t)SEQ*SEQ, (size_t)DM*SEQ, (size_t)SEQ*DM);
    if (emitT)
        k_scale_emit_tr<<<dim3(32, 16, nb), dim3(32, 8)>>>(
            p.Bh, p.Bl, p.part, p.Xh, p.Xl, p.Xth, p.Xtl);
    else
        k_scale_emit8<<<dim3(256, nb), 256>>>(p.Bh, p.Bl, p.part, p.Xh, p.Xl);
}

// batched cross (nb=32): B-operands Wkm/V2t and labels are 16-batch (band 15)
inline void cross_block(const float* bKc, const float* lbl, int nb, const Ptrs& p)
{
    proj(1, bKc, p.Wh, p.Wl, nb, p);
    k_gemm<0><<<dim3(8, 16, nb), 256, GEMM_SMEM_BYTES>>>(
        p.Wh, p.Wl, p.Wkmh, p.Wkml, p.Sc, nullptr, nullptr, nullptr, nullptr,
        nullptr, nullptr, 15, SEQ, SEQ, KD, (size_t)SEQ*KD, (size_t)SEQ*KD, (size_t)SEQ*SEQ);
    k_softmax<true><<<dim3(SEQ, nb), 256>>>(p.Sc, p.Sch, p.Scl, p.mask, lbl, 15);
    k_gemm<3><<<dim3(4, 16, nb), 256, GEMM_SMEM_BYTES>>>(
        p.Sch, p.Scl, p.V2th, p.V2tl, nullptr, p.Bh, p.Bl, p.Xh, p.Xl,
        p.mask, p.part, 15, SEQ, DM, SEQ, (size_t)SEQ*SEQ, (size_t)DM*SEQ, (size_t)SEQ*DM);
    k_cross_final_tr<<<dim3(32, 16, nb), dim3(32, 8)>>>(
        p.Xh, p.Xl, p.Bh, p.Bl, p.mask, p.part, p.Xth, p.Xtl);
}

} // namespace

extern "C" void kernel_launch(void* const* d_in, const int* in_sizes, int n_in,
                              void* d_out, int out_size)
{
    const float* train = (const float*)d_in[0];
    const float* test  = (const float*)d_in[1];
    const float* lbl   = (const float*)d_in[2];
    const float* WKs   = (const float*)d_in[3];
    const float* bKs   = (const float*)d_in[4];
    const float* WKc   = (const float*)d_in[5];
    const float* bKc   = (const float*)d_in[6];
    float* out = (float*)d_out;

    cudaFuncSetAttribute(k_gemm<0>, cudaFuncAttributeMaxDynamicSharedMemorySize, GEMM_SMEM_BYTES);
    cudaFuncSetAttribute(k_gemm<1>, cudaFuncAttributeMaxDynamicSharedMemorySize, GEMM_SMEM_BYTES);
    cudaFuncSetAttribute(k_gemm<2>, cudaFuncAttributeMaxDynamicSharedMemorySize, GEMM_SMEM_BYTES);
    cudaFuncSetAttribute(k_gemm<3>, cudaFuncAttributeMaxDynamicSharedMemorySize, GEMM_SMEM_BYTES);

    Ptrs p;
    cudaGetSymbolAddress((void**)&p.Sc,   g_Sc);
    cudaGetSymbolAddress((void**)&p.mask, g_mask);
    cudaGetSymbolAddress((void**)&p.part, g_part);
    cudaGetSymbolAddress((void**)&p.Xh,   g_Xh);
    cudaGetSymbolAddress((void**)&p.Xl,   g_Xl);
    cudaGetSymbolAddress((void**)&p.Xth,  g_Xth);
    cudaGetSymbolAddress((void**)&p.Xtl,  g_Xtl);
    cudaGetSymbolAddress((void**)&p.V2th, g_V2th);
    cudaGetSymbolAddress((void**)&p.V2tl, g_V2tl);
    cudaGetSymbolAddress((void**)&p.Bh,   g_Bh);
    cudaGetSymbolAddress((void**)&p.Bl,   g_Bl);
    cudaGetSymbolAddress((void**)&p.Wh,   g_Wh);
    cudaGetSymbolAddress((void**)&p.Wl,   g_Wl);
    cudaGetSymbolAddress((void**)&p.Wkmh, g_Wkmh);
    cudaGetSymbolAddress((void**)&p.Wkml, g_Wkml);
    cudaGetSymbolAddress((void**)&p.Sch,  g_Sch);
    cudaGetSymbolAddress((void**)&p.Scl,  g_Scl);
    cudaGetSymbolAddress((void**)&p.WKth, g_WKth);
    cudaGetSymbolAddress((void**)&p.WKtl, g_WKtl);

    // weight transpose + split
    k_split_wt<<<dim3(4, 16), dim3(32, 8)>>>(WKs, p.WKth,         p.WKtl);
    k_split_wt<<<dim3(4, 16), dim3(32, 8)>>>(WKc, p.WKth + KD*DM, p.WKtl + KD*DM);

    // ---- encoder (16 batches): 2x self-attn on train_feat; memory in Xh/Xl[0..16)
    k_trans_in<<<dim3(32, 16, BATCH), dim3(32, 8)>>>(train, p.Xh, p.Xl, p.Xth, p.Xtl);
    self_block(bKs, true,  BATCH, p);    // emits Xt for the second self block
    self_block(bKs, false, BATCH, p);

    // cross-attn invariants from memory (16 batches)
    proj(1, bKc, p.Wkmh, p.Wkml, BATCH, p);                            // wk(memory)
    k_v2t<<<dim3(32, 16, BATCH), dim3(32, 8)>>>(p.Xh, p.Xl, lbl, p.V2th, p.V2tl);

    // ---- batched decoders (32 batches): train -> 0..15, test -> 16..31 ----
    const size_t ho = (size_t)BATCH * EPB;   // half offset in bf16 activation tensors
    k_trans_in<<<dim3(32, 16, BATCH), dim3(32, 8)>>>(train, p.Xh, p.Xl, p.Xth, p.Xtl);
    k_trans_in<<<dim3(32, 16, BATCH), dim3(32, 8)>>>(test,  p.Xh + ho, p.Xl + ho,
                                                           p.Xth + ho, p.Xtl + ho);
    for (int l = 0; l < 2; l++) {
        self_block(bKs, false, DB, p);    // Xt from trans_in / cross_final_tr
        cross_block(bKc, lbl, DB, p);     // emits Xt for next self
    }
    // out is [2,B,D,H,W] = contiguous [32][D][S]
    k_trans_out<<<dim3(32, 16, DB), dim3(32, 8)>>>(p.Xh, p.Xl, out);
}

// round 16
// speedup vs baseline: 1.1546x; 1.1546x over previous
#include <cuda_runtime.h>
#include <cuda_bf16.h>
#include <math.h>
#include <stdint.h>

#define BATCH 16
#define DB    32                 // batched decoders: train(0..15) + test(16..31)
#define SEQ   1024
#define DM    512
#define KD    128
#define TEMP_F 30.0f
#define EPB   (SEQ*DM)
#define PS    1024               // part-section stride (32 batches x 32 tiles)
#define NORM_SCALE_F 0.011048543456039806f   // sqrt(1/(512*16))

typedef __nv_bfloat16 bf16;

// ---------------- scratch (static device memory; allocation-free) ----------
__device__ __align__(16) float g_Sc  [DB*SEQ*SEQ];                           // fp32 scores
__device__ __align__(16) bf16 g_Xh  [DB*SEQ*DM], g_Xl  [DB*SEQ*DM];          // x   [b][S][D]
__device__ __align__(16) bf16 g_Xth [DB*SEQ*DM], g_Xtl [DB*SEQ*DM];          // x^T [b][D][S]
__device__ __align__(16) bf16 g_V2th[BATCH*SEQ*DM], g_V2tl[BATCH*SEQ*DM];    // (mem*lbl)^T
__device__ __align__(16) bf16 g_Bh  [DB*SEQ*DM], g_Bl  [DB*SEQ*DM];          // residual sums
__device__ __align__(16) bf16 g_Wh  [DB*SEQ*KD], g_Wl  [DB*SEQ*KD];
__device__ __align__(16) bf16 g_Wkmh[BATCH*SEQ*KD], g_Wkml[BATCH*SEQ*KD];
__device__ __align__(16) bf16 g_Sch [DB*SEQ*SEQ], g_Scl[DB*SEQ*SEQ];
__device__ __align__(16) bf16 g_WKth[2*KD*DM], g_WKtl[2*KD*DM];              // WK^T [K][D]
__device__ float g_mask[DB*SEQ];
__device__ float g_part[3*PS];

__device__ __forceinline__ void bsplit(float x, bf16& h, bf16& l)
{
    bf16 hh = __float2bfloat16(x);
    h = hh;
    l = __float2bfloat16(x - __bfloat162float(hh));
}
__device__ __forceinline__ float upk0(uint32_t u){ return __bfloat162float(((__nv_bfloat162*)&u)->x); }
__device__ __forceinline__ float upk1(uint32_t u){ return __bfloat162float(((__nv_bfloat162*)&u)->y); }
__device__ __forceinline__ uint32_t pack2(bf16 a, bf16 b){
    __nv_bfloat162 t; t.x = a; t.y = b; return *(uint32_t*)&t;
}

// ====================== pure-bf16 3-pass tensor-core GEMM ==================
// C = (Ah+Al) @ (Bh+Bl)^T (drop Al*Bl).  A:[M,K], B:[N,K], both row-major.
// Block 128x128, BK=64 (halved sync count vs BK=32; identical MMA order),
// 2-stage cp.async, 8 warps (2x4), warp tile 64x32, mma m16n8k16.
// B batch index = blockIdx.z & zband (cross-attn B operands are 16-batch).
// EPI: 0 = fp32 C store; 1 = bias + row-L2 + bf16 split (proj, N=128, grid.x=1)
//      2 = +residual x, emit splits, sumsq partials (self AV)
//      3 = +residual x, emit splits, Sbb/Saa/Sab partials (cross t3)
//      4 = fp32 C store, symmetric (A==B): compute by<=bx, mirror off-diag

__device__ __forceinline__ void mma_bf16(float* c, const uint32_t* a, const uint32_t* b)
{
    asm volatile(
        "mma.sync.aligned.m16n8k16.row.col.f32.bf16.bf16.f32 "
        "{%0,%1,%2,%3},{%4,%5,%6,%7},{%8,%9},{%0,%1,%2,%3};"
        : "+f"(c[0]), "+f"(c[1]), "+f"(c[2]), "+f"(c[3])
        : "r"(a[0]), "r"(a[1]), "r"(a[2]), "r"(a[3]), "r"(b[0]), "r"(b[1]));
}

#define CP_ASYNC16(dst_u32, src_ptr) \
    asm volatile("cp.async.cg.shared.global [%0], [%1], 16;\n" :: "r"(dst_u32), "l"(src_ptr))
#define CP_COMMIT()  asm volatile("cp.async.commit_group;\n" ::)
#define CP_WAIT_1()  asm volatile("cp.async.wait_group 1;\n" ::)
#define CP_WAIT_0()  asm volatile("cp.async.wait_group 0;\n" ::)

// per stage 4 tiles (Ah,Al,Bh,Bl), each [128 rows][36 words] (64 bf16 + 4 pad)
#define ROW_W    36
#define TILE_W   (128*ROW_W)                 // 4608 words
#define STAGE_W  (4*TILE_W)                  // 18432 words
#define GEMM_SMEM_BYTES (2*STAGE_W*4)        // 147456 B (1 CTA/SM; covers mirror)

template<int EPI>
__global__ void __launch_bounds__(256, 1)
k_gemm(const bf16* __restrict__ Ahg, const bf16* __restrict__ Alg,
       const bf16* __restrict__ Bhg, const bf16* __restrict__ Blg,
       float* __restrict__ Cg, bf16* __restrict__ OH, bf16* __restrict__ OL,
       const bf16* __restrict__ RXh, const bf16* __restrict__ RXl,
       const float* __restrict__ bm_aux,   // EPI1: bias[N]; EPI3: mask[b*SEQ]
       float* __restrict__ part, int zband,
       int M, int N, int K, size_t sA, size_t sB, size_t sC)
{
    if (EPI == 4 && blockIdx.y > blockIdx.x) return;   // lower triangle mirrored

    extern __shared__ uint32_t sm[];
    const bf16* Ah = Ahg + (size_t)blockIdx.z * sA;
    const bf16* Al = Alg + (size_t)blockIdx.z * sA;
    const bf16* Bh = Bhg + (size_t)(blockIdx.z & zband) * sB;
    const bf16* Bl = Blg + (size_t)(blockIdx.z & zband) * sB;

    const int bm = blockIdx.y * 128;
    const int bn = blockIdx.x * 128;
    const int tid  = threadIdx.x;
    const int lane = tid & 31;
    const int warp = tid >> 5;
    const int wm = (warp & 1) * 64;
    const int wn = (warp >> 1) * 32;
    const int qid = lane >> 2;
    const int tig = lane & 3;

    const uint32_t sbase = (uint32_t)__cvta_generic_to_shared(sm);

    auto load_stage = [&](int st, int k0) {
        uint32_t stb = sbase + st * (STAGE_W * 4);
        #pragma unroll
        for (int h = 0; h < 4; h++) {
            int idx = tid + h * 256;          // 0..1023
            int rr = idx >> 3, cc = idx & 7;  // row 0..127, 16B chunk 0..7
            uint32_t woff = (rr * ROW_W + cc * 4) * 4;
            size_t ga = (size_t)(bm + rr) * K + k0 + cc * 8;
            size_t gb = (size_t)(bn + rr) * K + k0 + cc * 8;
            CP_ASYNC16(stb + 0*TILE_W*4 + woff, Ah + ga);
            CP_ASYNC16(stb + 1*TILE_W*4 + woff, Al + ga);
            CP_ASYNC16(stb + 2*TILE_W*4 + woff, Bh + gb);
            CP_ASYNC16(stb + 3*TILE_W*4 + woff, Bl + gb);
        }
        CP_COMMIT();
    };

    float acc[4][4][4] = {};
    const int nIter = K >> 6;
    load_stage(0, 0);

    for (int it = 0; it < nIter; ++it) {
        if (it + 1 < nIter) { load_stage((it + 1) & 1, (it + 1) * 64); CP_WAIT_1(); }
        else                { CP_WAIT_0(); }
        __syncthreads();

        const uint32_t* As_h = sm + (it & 1) * STAGE_W;
        const uint32_t* As_l = As_h + TILE_W;
        const uint32_t* Bs_h = As_h + 2*TILE_W;
        const uint32_t* Bs_l = As_h + 3*TILE_W;

        #pragma unroll
        for (int ks = 0; ks < 4; ks++) {
            const int kw = ks * 8 + tig;
            uint32_t ah[4][4], bh[4][2], bl[4][2];
            #pragma unroll
            for (int mi = 0; mi < 4; mi++) {
                int b0 = (wm + mi*16 + qid) * ROW_W + kw;
                ah[mi][0] = As_h[b0];           ah[mi][1] = As_h[b0 + 8*ROW_W];
                ah[mi][2] = As_h[b0 + 4];       ah[mi][3] = As_h[b0 + 8*ROW_W + 4];
            }
            #pragma unroll
            for (int ni = 0; ni < 4; ni++) {
                int b0 = (wn + ni*8 + qid) * ROW_W + kw;
                bh[ni][0] = Bs_h[b0];  bh[ni][1] = Bs_h[b0 + 4];
                bl[ni][0] = Bs_l[b0];  bl[ni][1] = Bs_l[b0 + 4];
            }
            #pragma unroll
            for (int mi = 0; mi < 4; mi++)
                #pragma unroll
                for (int ni = 0; ni < 4; ni++)
                    mma_bf16(acc[mi][ni], ah[mi], bh[ni]);
            #pragma unroll
            for (int mi = 0; mi < 4; mi++)
                #pragma unroll
                for (int ni = 0; ni < 4; ni++)
                    mma_bf16(acc[mi][ni], ah[mi], bl[ni]);
            uint32_t al[4][4];
            #pragma unroll
            for (int mi = 0; mi < 4; mi++) {
                int b0 = (wm + mi*16 + qid) * ROW_W + kw;
                al[mi][0] = As_l[b0];           al[mi][1] = As_l[b0 + 8*ROW_W];
                al[mi][2] = As_l[b0 + 4];       al[mi][3] = As_l[b0 + 8*ROW_W + 4];
            }
            #pragma unroll
            for (int mi = 0; mi < 4; mi++)
                #pragma unroll
                for (int ni = 0; ni < 4; ni++)
                    mma_bf16(acc[mi][ni], al[mi], bh[ni]);
        }
        __syncthreads();
    }

    const size_t zC = (size_t)blockIdx.z * sC;

    if (EPI == 0 || EPI == 4) {
        float* C = Cg + zC;
        #pragma unroll
        for (int mi = 0; mi < 4; mi++)
            #pragma unroll
            for (int ni = 0; ni < 4; ni++) {
                const int r = bm + wm + mi * 16 + qid;
                const int c = bn + wn + ni * 8 + 2 * tig;
                *(float2*)&C[(size_t)r * N + c]       = make_float2(acc[mi][ni][0], acc[mi][ni][1]);
                *(float2*)&C[(size_t)(r + 8) * N + c] = make_float2(acc[mi][ni][2], acc[mi][ni][3]);
            }
        if (EPI == 4 && blockIdx.y != blockIdx.x) {
            float* T = (float*)sm;   // [128][132]
            #pragma unroll
            for (int mi = 0; mi < 4; mi++)
                #pragma unroll
                for (int ni = 0; ni < 4; ni++) {
                    const int rl = wm + mi * 16 + qid;
                    const int cl = wn + ni * 8 + 2 * tig;
                    T[ cl      * 132 + rl]     = acc[mi][ni][0];
                    T[(cl + 1) * 132 + rl]     = acc[mi][ni][1];
                    T[ cl      * 132 + rl + 8] = acc[mi][ni][2];
                    T[(cl + 1) * 132 + rl + 8] = acc[mi][ni][3];
                }
            __syncthreads();
            #pragma unroll 8
            for (int i = 0; i < 64; i++) {
                int lin = tid + i * 256;
                int col = lin >> 7, row = lin & 127;
                C[(size_t)(bn + col) * N + bm + row] = T[col * 132 + row];
            }
        }
    }
    else if (EPI == 1) {
        float* srow = (float*)sm;   // [128][4]
        float rs[4][2];
        #pragma unroll
        for (int mi = 0; mi < 4; mi++) { rs[mi][0] = 0.f; rs[mi][1] = 0.f; }
        #pragma unroll
        for (int mi = 0; mi < 4; mi++)
            #pragma unroll
            for (int ni = 0; ni < 4; ni++) {
                const int c = bn + wn + ni * 8 + 2 * tig;
                float b0 = bm_aux[c], b1 = bm_aux[c + 1];
                acc[mi][ni][0] += b0; acc[mi][ni][1] += b1;
                acc[mi][ni][2] += b0; acc[mi][ni][3] += b1;
                rs[mi][0] += acc[mi][ni][0]*acc[mi][ni][0] + acc[mi][ni][1]*acc[mi][ni][1];
                rs[mi][1] += acc[mi][ni][2]*acc[mi][ni][2] + acc[mi][ni][3]*acc[mi][ni][3];
            }
        #pragma unroll
        for (int mi = 0; mi < 4; mi++)
            #pragma unroll
            for (int h = 0; h < 2; h++) {
                float v = rs[mi][h];
                v += __shfl_xor_sync(0xffffffffu, v, 1);
                v += __shfl_xor_sync(0xffffffffu, v, 2);
                rs[mi][h] = v;
            }
        if (tig == 0)
            #pragma unroll
            for (int mi = 0; mi < 4; mi++)
                #pragma unroll
                for (int h = 0; h < 2; h++)
                    srow[(wm + mi*16 + qid + h*8) * 4 + (wn >> 5)] = rs[mi][h];
        __syncthreads();
        #pragma unroll
        for (int mi = 0; mi < 4; mi++)
            #pragma unroll
            for (int h = 0; h < 2; h++) {
                int rl = wm + mi*16 + qid + h*8;
                float tot = srow[rl*4] + srow[rl*4+1] + srow[rl*4+2] + srow[rl*4+3];
                float inv = 1.f / fmaxf(sqrtf(tot), 1e-12f);
                #pragma unroll
                for (int ni = 0; ni < 4; ni++) {
                    const int c = bn + wn + ni * 8 + 2 * tig;
                    size_t i = zC + (size_t)(bm + rl) * N + c;
                    bf16 h0,l0,h1,l1;
                    bsplit(acc[mi][ni][2*h]   * inv, h0, l0);
                    bsplit(acc[mi][ni][2*h+1] * inv, h1, l1);
                    *(uint32_t*)(OH + i) = pack2(h0, h1);
                    *(uint32_t*)(OL + i) = pack2(l0, l1);
                }
            }
    }
    else {  // EPI 2 / 3: residual add + split emit + partial sums
        const bf16* Xh = RXh + zC;
        const bf16* Xl = RXl + zC;
        float saa = 0.f, sab = 0.f, sbb = 0.f;
        #pragma unroll
        for (int mi = 0; mi < 4; mi++) {
            const int r0 = bm + wm + mi * 16 + qid;
            float mk0 = 0.f, mk1 = 0.f;
            if (EPI == 3) {
                mk0 = bm_aux[blockIdx.z * SEQ + r0];
                mk1 = bm_aux[blockIdx.z * SEQ + r0 + 8];
            }
            #pragma unroll
            for (int ni = 0; ni < 4; ni++) {
                const int c = bn + wn + ni * 8 + 2 * tig;
                size_t i0 = (size_t)r0 * N + c;
                size_t i1 = i0 + (size_t)8 * N;
                uint32_t xh0 = *(const uint32_t*)(Xh + i0), xl0 = *(const uint32_t*)(Xl + i0);
                uint32_t xh1 = *(const uint32_t*)(Xh + i1), xl1 = *(const uint32_t*)(Xl + i1);
                float x00 = upk0(xh0)+upk0(xl0), x01 = upk1(xh0)+upk1(xl0);
                float x10 = upk0(xh1)+upk0(xl1), x11 = upk1(xh1)+upk1(xl1);
                float v00 = acc[mi][ni][0] + x00, v01 = acc[mi][ni][1] + x01;
                float v10 = acc[mi][ni][2] + x10, v11 = acc[mi][ni][3] + x11;
                sbb += v00*v00 + v01*v01 + v10*v10 + v11*v11;
                if (EPI == 3) {
                    float a00 = x00*mk0, a01 = x01*mk0, a10 = x10*mk1, a11 = x11*mk1;
                    saa += a00*a00 + a01*a01 + a10*a10 + a11*a11;
                    sab += a00*v00 + a01*v01 + a10*v10 + a11*v11;
                }
                bf16 h0,l0,h1,l1;
                bsplit(v00, h0, l0); bsplit(v01, h1, l1);
                *(uint32_t*)(OH + zC + i0) = pack2(h0, h1);
                *(uint32_t*)(OL + zC + i0) = pack2(l0, l1);
                bsplit(v10, h0, l0); bsplit(v11, h1, l1);
                *(uint32_t*)(OH + zC + i1) = pack2(h0, h1);
                *(uint32_t*)(OL + zC + i1) = pack2(l0, l1);
            }
        }
        float* red = (float*)sm;   // [3][8]
        #pragma unroll
        for (int o = 16; o; o >>= 1) {
            sbb += __shfl_xor_sync(0xffffffffu, sbb, o);
            if (EPI == 3) {
                saa += __shfl_xor_sync(0xffffffffu, saa, o);
                sab += __shfl_xor_sync(0xffffffffu, sab, o);
            }
        }
        if (lane == 0) {
            red[warp] = sbb;
            if (EPI == 3) { red[8 + warp] = saa; red[16 + warp] = sab; }
        }
        __syncthreads();
        if (tid == 0) {
            const int tileId = blockIdx.y * gridDim.x + blockIdx.x;   // 0..31
            float tb = 0.f; for (int i = 0; i < 8; i++) tb += red[i];
            part[blockIdx.z * 32 + tileId] = tb;
            if (EPI == 3) {
                float ta = 0.f, tc = 0.f;
                for (int i = 0; i < 8; i++) { ta += red[8+i]; tc += red[16+i]; }
                part[PS   + blockIdx.z * 32 + tileId] = ta;   // Saa
                part[2*PS + blockIdx.z * 32 + tileId] = tc;   // Sab
            }
        }
    }
}

// ---------------- weight transpose + split: WK[D][K] -> WKt[K][D] ----------
__global__ void k_split_wt(const float* __restrict__ Wk, bf16* __restrict__ th,
                           bf16* __restrict__ tl)
{
    __shared__ float tile[32][33];
    int k0 = blockIdx.x * 32, d0 = blockIdx.y * 32;
    for (int r = threadIdx.y; r < 32; r += 8)
        tile[r][threadIdx.x] = Wk[(size_t)(d0 + r) * KD + k0 + threadIdx.x];
    __syncthreads();
    for (int r = threadIdx.y; r < 32; r += 8) {
        size_t idx = (size_t)(k0 + r) * DM + d0 + threadIdx.x;
        bsplit(tile[threadIdx.x][r], th[idx], tl[idx]);
    }
}

// ---------------- input: [b,D,S] fp32 -> X splits [b,S,D] + Xt [b,D,S] -----
__global__ void k_trans_in(const float* __restrict__ in,
                           bf16* __restrict__ Xh, bf16* __restrict__ Xl,
                           bf16* __restrict__ Xth, bf16* __restrict__ Xtl)
{
    __shared__ bf16 tH[32][33], tL[32][33];
    int b = blockIdx.z;
    int d0 = blockIdx.y * 32, s0 = blockIdx.x * 32;
    for (int r = threadIdx.y; r < 32; r += 8) {
        size_t ti = ((size_t)b*DM + d0 + r) * SEQ + s0 + threadIdx.x;
        bf16 h, l;
        bsplit(in[ti], h, l);
        Xth[ti] = h; Xtl[ti] = l;     // input is already [D][S]
        tH[r][threadIdx.x] = h; tL[r][threadIdx.x] = l;
    }
    __syncthreads();
    for (int r = threadIdx.y; r < 32; r += 8) {
        size_t idx = ((size_t)b*SEQ + s0 + r) * DM + d0 + threadIdx.x;
        Xh[idx] = tH[threadIdx.x][r];
        Xl[idx] = tL[threadIdx.x][r];
    }
}

// ---------------- output transpose: splits [b,S,D] -> fp32 [b,D,S] ---------
__global__ void k_trans_out(const bf16* __restrict__ Xh, const bf16* __restrict__ Xl,
                            float* __restrict__ out)
{
    __shared__ float tile[32][33];
    int b = blockIdx.z;
    int d0 = blockIdx.y * 32, s0 = blockIdx.x * 32;
    for (int r = threadIdx.y; r < 32; r += 8) {
        size_t idx = ((size_t)b*SEQ + s0 + r) * DM + d0 + threadIdx.x;
        tile[r][threadIdx.x] = __bfloat162float(Xh[idx]) + __bfloat162float(Xl[idx]);
    }
    __syncthreads();
    for (int r = threadIdx.y; r < 32; r += 8)
        out[((size_t)b*DM + d0 + r) * SEQ + s0 + threadIdx.x] = tile[threadIdx.x][r];
}

// ---------------- V2^T: (mem * label) transposed + split --------------------
__global__ void k_v2t(const bf16* __restrict__ Mh, const bf16* __restrict__ Ml,
                      const float* __restrict__ lbl,
                      bf16* __restrict__ th, bf16* __restrict__ tl)
{
    __shared__ float tile[32][33];
    int b = blockIdx.z;
    int s0 = blockIdx.x * 32, d0 = blockIdx.y * 32;
    for (int r = threadIdx.y; r < 32; r += 8) {
        size_t idx = ((size_t)b*SEQ + s0 + r) * DM + d0 + threadIdx.x;
        float v = __bfloat162float(Mh[idx]) + __bfloat162float(Ml[idx]);
        tile[r][threadIdx.x] = v * lbl[b*SEQ + s0 + r];
    }
    __syncthreads();
    for (int r = threadIdx.y; r < 32; r += 8) {
        size_t idx = ((size_t)b*DM + d0 + r) * SEQ + s0 + threadIdx.x;
        bsplit(tile[threadIdx.x][r], th[idx], tl[idx]);
    }
}

// ---------------- softmax (optionally fused mask GEMV) ----------------------
template<bool MASK>
__global__ void k_softmax(const float* __restrict__ Sc, bf16* __restrict__ Ph,
                          bf16* __restrict__ Pl, float* __restrict__ mask,
                          const float* __restrict__ lbl, int lband)
{
    __shared__ float sh1[8], sh2[8];
    int b = blockIdx.y, q = blockIdx.x, t = threadIdx.x;   // 256 threads
    size_t ro = ((size_t)b*SEQ + q) * SEQ;
    float4 v = reinterpret_cast<const float4*>(Sc + ro)[t];
    v.x *= TEMP_F; v.y *= TEMP_F; v.z *= TEMP_F; v.w *= TEMP_F;
    float m = fmaxf(fmaxf(v.x, v.y), fmaxf(v.z, v.w));
    #pragma unroll
    for (int o = 16; o; o >>= 1) m = fmaxf(m, __shfl_xor_sync(0xffffffffu, m, o));
    if ((t & 31) == 0) sh1[t >> 5] = m;
    __syncthreads();
    m = fmaxf(fmaxf(fmaxf(sh1[0], sh1[1]), fmaxf(sh1[2], sh1[3])),
              fmaxf(fmaxf(sh1[4], sh1[5]), fmaxf(sh1[6], sh1[7])));
    v.x = __expf(v.x - m); v.y = __expf(v.y - m);
    v.z = __expf(v.z - m); v.w = __expf(v.w - m);
    float sum = v.x + v.y + v.z + v.w;
    #pragma unroll
    for (int o = 16; o; o >>= 1) sum += __shfl_xor_sync(0xffffffffu, sum, o);
    if ((t & 31) == 0) sh2[t >> 5] = sum;
    __syncthreads();
    sum = sh2[0]+sh2[1]+sh2[2]+sh2[3]+sh2[4]+sh2[5]+sh2[6]+sh2[7];
    float inv = 1.f / sum;
    float p0 = v.x*inv, p1 = v.y*inv, p2 = v.z*inv, p3 = v.w*inv;
    bf16 h0,l0,h1,l1,h2,l2,h3,l3;
    bsplit(p0,h0,l0); bsplit(p1,h1,l1); bsplit(p2,h2,l2); bsplit(p3,h3,l3);
    uint2 uh; uh.x = pack2(h0,h1); uh.y = pack2(h2,h3);
    uint2 ul; ul.x = pack2(l0,l1); ul.y = pack2(l2,l3);
    *(uint2*)(Ph + ro + 4*t) = uh;
    *(uint2*)(Pl + ro + 4*t) = ul;
    if (MASK) {
        float4 L = reinterpret_cast<const float4*>(lbl + (size_t)(b & lband)*SEQ)[t];
        float s = p0*L.x + p1*L.y + p2*L.z + p3*L.w;
        #pragma unroll
        for (int o = 16; o; o >>= 1) s += __shfl_xor_sync(0xffffffffu, s, o);
        __syncthreads();
        if ((t & 31) == 0) sh1[t >> 5] = s;
        __syncthreads();
        if (t == 0)
            mask[b*SEQ + q] = sh1[0]+sh1[1]+sh1[2]+sh1[3]+sh1[4]+sh1[5]+sh1[6]+sh1[7];
    }
}

// ---------------- self-norm finalize: linear (no Xt emit) -------------------
__global__ void k_scale_emit8(const bf16* __restrict__ Bh, const bf16* __restrict__ Bl,
                              const float* __restrict__ part,
                              bf16* __restrict__ Xh, bf16* __restrict__ Xl)
{
    int b = blockIdx.y;
    float s = 0.f;
    #pragma unroll
    for (int i = 0; i < 32; i++) s += part[b*32 + i];
    float f = NORM_SCALE_F * sqrtf(524288.f / (s + 1e-5f));
    size_t i = (size_t)b*EPB + (size_t)blockIdx.x*2048 + threadIdx.x*8;
    uint4 uh = *(const uint4*)(Bh + i);
    uint4 ul = *(const uint4*)(Bl + i);
    uint32_t oh[4], ol[4];
    const uint32_t* ph = (const uint32_t*)&uh;
    const uint32_t* pl = (const uint32_t*)&ul;
    #pragma unroll
    for (int j = 0; j < 4; j++) {
        float v0 = (upk0(ph[j]) + upk0(pl[j])) * f;
        float v1 = (upk1(ph[j]) + upk1(pl[j])) * f;
        bf16 h0,l0,h1,l1;
        bsplit(v0,h0,l0); bsplit(v1,h1,l1);
        oh[j] = pack2(h0,h1); ol[j] = pack2(l0,l1);
    }
    *(uint4*)(Xh + i) = *(uint4*)oh;
    *(uint4*)(Xl + i) = *(uint4*)ol;
}

// ---------------- self-norm finalize: tiled, emits Xt too -------------------
__global__ void k_scale_emit_tr(const bf16* __restrict__ Bh, const bf16* __restrict__ Bl,
                                const float* __restrict__ part,
                                bf16* __restrict__ Xh, bf16* __restrict__ Xl,
                                bf16* __restrict__ Xth, bf16* __restrict__ Xtl)
{
    __shared__ bf16 tH[32][33], tL[32][33];
    int b = blockIdx.z;
    float s = 0.f;
    #pragma unroll
    for (int i = 0; i < 32; i++) s += part[b*32 + i];
    float f = NORM_SCALE_F * sqrtf(524288.f / (s + 1e-5f));
    int s0 = blockIdx.x * 32, d0 = blockIdx.y * 32;
    for (int r = threadIdx.y; r < 32; r += 8) {
        size_t idx = ((size_t)b*SEQ + s0 + r) * DM + d0 + threadIdx.x;
        float v = (__bfloat162float(Bh[idx]) + __bfloat162float(Bl[idx])) * f;
        bf16 h, l; bsplit(v, h, l);
        Xh[idx] = h; Xl[idx] = l;
        tH[r][threadIdx.x] = h; tL[r][threadIdx.x] = l;
    }
    __syncthreads();
    for (int r = threadIdx.y; r < 32; r += 8) {
        size_t idx = ((size_t)b*DM + d0 + r) * SEQ + s0 + threadIdx.x;
        Xth[idx] = tH[threadIdx.x][r];
        Xtl[idx] = tL[threadIdx.x][r];
    }
}

// ---------------- cross finalize: tiled, factors inline, emits Xt -----------
__global__ void k_cross_final_tr(bf16* __restrict__ Xh, bf16* __restrict__ Xl,
                                 const bf16* __restrict__ Bh, const bf16* __restrict__ Bl,
                                 const float* __restrict__ mask,
                                 const float* __restrict__ part,
                                 bf16* __restrict__ Xth, bf16* __restrict__ Xtl)
{
    __shared__ bf16 tH[32][33], tL[32][33];
    int b = blockIdx.z;
    float sbb = 0.f, saa = 0.f, sab = 0.f;
    #pragma unroll
    for (int i = 0; i < 32; i++) {
        sbb += part[b*32 + i];
        saa += part[PS   + b*32 + i];
        sab += part[2*PS + b*32 + i];
    }
    float f2 = NORM_SCALE_F * sqrtf(524288.f / (saa + 1e-5f));
    float f4 = NORM_SCALE_F * sqrtf(524288.f / (sbb + 1e-5f));
    float sf = f2*f2*saa + 2.f*f2*f4*sab + f4*f4*sbb;
    float F  = NORM_SCALE_F * sqrtf(524288.f / (sf + 1e-5f));
    float ca = F * f2, cb = F * f4;

    int s0 = blockIdx.x * 32, d0 = blockIdx.y * 32;
    for (int r = threadIdx.y; r < 32; r += 8) {
        size_t idx = ((size_t)b*SEQ + s0 + r) * DM + d0 + threadIdx.x;
        float camk = ca * mask[b*SEQ + s0 + r];
        float x = __bfloat162float(Xh[idx]) + __bfloat162float(Xl[idx]);
        float bv = __bfloat162float(Bh[idx]) + __bfloat162float(Bl[idx]);
        float v = camk * x + cb * bv;
        bf16 h, l; bsplit(v, h, l);
        Xh[idx] = h; Xl[idx] = l;
        tH[r][threadIdx.x] = h; tL[r][threadIdx.x] = l;
    }
    __syncthreads();
    for (int r = threadIdx.y; r < 32; r += 8) {
        size_t idx = ((size_t)b*DM + d0 + r) * SEQ + s0 + threadIdx.x;
        Xth[idx] = tH[threadIdx.x][r];
        Xtl[idx] = tL[threadIdx.x][r];
    }
}

// =================== host-side orchestration ===============================
namespace {

struct Ptrs {
    float *Sc, *mask, *part;
    bf16 *Xh, *Xl, *Xth, *Xtl, *V2th, *V2tl, *Bh, *Bl,
         *Wh, *Wl, *Wkmh, *Wkml, *Sch, *Scl, *WKth, *WKtl;
};

inline void proj(int wsel, const float* bK, bf16* outH, bf16* outL, int nb, const Ptrs& p)
{
    k_gemm<1><<<dim3(1, 8, nb), 256, GEMM_SMEM_BYTES>>>(
        p.Xh, p.Xl, p.WKth + (size_t)wsel*KD*DM, p.WKtl + (size_t)wsel*KD*DM,
        nullptr, outH, outL, nullptr, nullptr, bK, nullptr, 0,
        SEQ, KD, DM, (size_t)SEQ*DM, 0, (size_t)SEQ*KD);
}

// Xth/Xtl must already hold the transpose of the current X (producer-emitted)
inline void self_block(const float* bKs, bool emitT, int nb, const Ptrs& p)
{
    proj(0, bKs, p.Wh, p.Wl, nb, p);
    k_gemm<4><<<dim3(8, 8, nb), 256, GEMM_SMEM_BYTES>>>(     // symmetric scores
        p.Wh, p.Wl, p.Wh, p.Wl, p.Sc, nullptr, nullptr, nullptr, nullptr,
        nullptr, nullptr, 31, SEQ, SEQ, KD, (size_t)SEQ*KD, (size_t)SEQ*KD, (size_t)SEQ*SEQ);
    k_softmax<false><<<dim3(SEQ, nb), 256>>>(p.Sc, p.Sch, p.Scl, nullptr, nullptr, 0);
    k_gemm<2><<<dim3(4, 8, nb), 256, GEMM_SMEM_BYTES>>>(
        p.Sch, p.Scl, p.Xth, p.Xtl, nullptr, p.Bh, p.Bl, p.Xh, p.Xl,
        nullptr, p.part, 31, SEQ, DM, SEQ, (size_t)SEQ*SEQ, (size_t)DM*SEQ, (size_t)SEQ*DM);
    if (emitT)
        k_scale_emit_tr<<<dim3(32, 16, nb), dim3(32, 8)>>>(
            p.Bh, p.Bl, p.part, p.Xh, p.Xl, p.Xth, p.Xtl);
    else
        k_scale_emit8<<<dim3(256, nb), 256>>>(p.Bh, p.Bl, p.part, p.Xh, p.Xl);
}

// batched cross (nb=32): B-operands Wkm/V2t and labels are 16-batch (band 15)
inline void cross_block(const float* bKc, const float* lbl, int nb, const Ptrs& p)
{
    proj(1, bKc, p.Wh, p.Wl, nb, p);
    k_gemm<0><<<dim3(8, 8, nb), 256, GEMM_SMEM_BYTES>>>(
        p.Wh, p.Wl, p.Wkmh, p.Wkml, p.Sc, nullptr, nullptr, nullptr, nullptr,
        nullptr, nullptr, 15, SEQ, SEQ, KD, (size_t)SEQ*KD, (size_t)SEQ*KD, (size_t)SEQ*SEQ);
    k_softmax<true><<<dim3(SEQ, nb), 256>>>(p.Sc, p.Sch, p.Scl, p.mask, lbl, 15);
    k_gemm<3><<<dim3(4, 8, nb), 256, GEMM_SMEM_BYTES>>>(
        p.Sch, p.Scl, p.V2th, p.V2tl, nullptr, p.Bh, p.Bl, p.Xh, p.Xl,
        p.mask, p.part, 15, SEQ, DM, SEQ, (size_t)SEQ*SEQ, (size_t)DM*SEQ, (size_t)SEQ*DM);
    k_cross_final_tr<<<dim3(32, 16, nb), dim3(32, 8)>>>(
        p.Xh, p.Xl, p.Bh, p.Bl, p.mask, p.part, p.Xth, p.Xtl);
}

} // namespace

extern "C" void kernel_launch(void* const* d_in, const int* in_sizes, int n_in,
                              void* d_out, int out_size)
{
    const float* train = (const float*)d_in[0];
    const float* test  = (const float*)d_in[1];
    const float* lbl   = (const float*)d_in[2];
    const float* WKs   = (const float*)d_in[3];
    const float* bKs   = (const float*)d_in[4];
    const float* WKc   = (const float*)d_in[5];
    const float* bKc   = (const float*)d_in[6];
    float* out = (float*)d_out;

    cudaFuncSetAttribute(k_gemm<0>, cudaFuncAttributeMaxDynamicSharedMemorySize, GEMM_SMEM_BYTES);
    cudaFuncSetAttribute(k_gemm<1>, cudaFuncAttributeMaxDynamicSharedMemorySize, GEMM_SMEM_BYTES);
    cudaFuncSetAttribute(k_gemm<2>, cudaFuncAttributeMaxDynamicSharedMemorySize, GEMM_SMEM_BYTES);
    cudaFuncSetAttribute(k_gemm<3>, cudaFuncAttributeMaxDynamicSharedMemorySize, GEMM_SMEM_BYTES);
    cudaFuncSetAttribute(k_gemm<4>, cudaFuncAttributeMaxDynamicSharedMemorySize, GEMM_SMEM_BYTES);

    Ptrs p;
    cudaGetSymbolAddress((void**)&p.Sc,   g_Sc);
    cudaGetSymbolAddress((void**)&p.mask, g_mask);
    cudaGetSymbolAddress((void**)&p.part, g_part);
    cudaGetSymbolAddress((void**)&p.Xh,   g_Xh);
    cudaGetSymbolAddress((void**)&p.Xl,   g_Xl);
    cudaGetSymbolAddress((void**)&p.Xth,  g_Xth);
    cudaGetSymbolAddress((void**)&p.Xtl,  g_Xtl);
    cudaGetSymbolAddress((void**)&p.V2th, g_V2th);
    cudaGetSymbolAddress((void**)&p.V2tl, g_V2tl);
    cudaGetSymbolAddress((void**)&p.Bh,   g_Bh);
    cudaGetSymbolAddress((void**)&p.Bl,   g_Bl);
    cudaGetSymbolAddress((void**)&p.Wh,   g_Wh);
    cudaGetSymbolAddress((void**)&p.Wl,   g_Wl);
    cudaGetSymbolAddress((void**)&p.Wkmh, g_Wkmh);
    cudaGetSymbolAddress((void**)&p.Wkml, g_Wkml);
    cudaGetSymbolAddress((void**)&p.Sch,  g_Sch);
    cudaGetSymbolAddress((void**)&p.Scl,  g_Scl);
    cudaGetSymbolAddress((void**)&p.WKth, g_WKth);
    cudaGetSymbolAddress((void**)&p.WKtl, g_WKtl);

    // weight transpose + split
    k_split_wt<<<dim3(4, 16), dim3(32, 8)>>>(WKs, p.WKth,         p.WKtl);
    k_split_wt<<<dim3(4, 16), dim3(32, 8)>>>(WKc, p.WKth + KD*DM, p.WKtl + KD*DM);

    // ---- encoder (16 batches): 2x self-attn on train_feat; memory in Xh/Xl[0..16)
    k_trans_in<<<dim3(32, 16, BATCH), dim3(32, 8)>>>(train, p.Xh, p.Xl, p.Xth, p.Xtl);
    self_block(bKs, true,  BATCH, p);    // emits Xt for the second self block
    self_block(bKs, false, BATCH, p);

    // cross-attn invariants from memory (16 batches)
    proj(1, bKc, p.Wkmh, p.Wkml, BATCH, p);                            // wk(memory)
    k_v2t<<<dim3(32, 16, BATCH), dim3(32, 8)>>>(p.Xh, p.Xl, lbl, p.V2th, p.V2tl);

    // ---- batched decoders (32 batches): train -> 0..15, test -> 16..31 ----
    const size_t ho = (size_t)BATCH * EPB;   // half offset in bf16 activation tensors
    k_trans_in<<<dim3(32, 16, BATCH), dim3(32, 8)>>>(train, p.Xh, p.Xl, p.Xth, p.Xtl);
    k_trans_in<<<dim3(32, 16, BATCH), dim3(32, 8)>>>(test,  p.Xh + ho, p.Xl + ho,
                                                           p.Xth + ho, p.Xtl + ho);
    for (int l = 0; l < 2; l++) {
        self_block(bKs, false, DB, p);    // Xt from trans_in / cross_final_tr
        cross_block(bKc, lbl, DB, p);     // emits Xt for next self
    }
    // out is [2,B,D,H,W] = contiguous [32][D][S]
    k_trans_out<<<dim3(32, 16, DB), dim3(32, 8)>>>(p.Xh, p.Xl, out);
}

// round 17
// speedup vs baseline: 1.2566x; 1.0883x over previous
#include <cuda_runtime.h>
#include <cuda_bf16.h>
#include <math.h>
#include <stdint.h>

#define BATCH 16
#define SL    48                 // batch slots: enc 0..15 | train-dec 16..31 | test-dec 32..47
#define TEMP_F 30.0f
#define SEQ   1024
#define DM    512
#define KD    128
#define EPB   (SEQ*DM)
#define PS    1024               // part-section stride (32 z x 32 tiles)
#define NORM_SCALE_F 0.011048543456039806f   // sqrt(1/(512*16))

typedef __nv_bfloat16 bf16;

// ---------------- scratch (static device memory; allocation-free) ----------
__device__ __align__(16) float g_Sc  [SL*SEQ*SEQ];                           // fp32 scores
__device__ __align__(16) bf16 g_Xh  [SL*SEQ*DM], g_Xl  [SL*SEQ*DM];          // x   [b][S][D]
__device__ __align__(16) bf16 g_Xth [SL*SEQ*DM], g_Xtl [SL*SEQ*DM];          // x^T [b][D][S]
__device__ __align__(16) bf16 g_V2th[BATCH*SEQ*DM], g_V2tl[BATCH*SEQ*DM];    // (mem*lbl)^T
__device__ __align__(16) bf16 g_Bh  [SL*SEQ*DM], g_Bl  [SL*SEQ*DM];          // residual sums
__device__ __align__(16) bf16 g_Wh  [SL*SEQ*KD], g_Wl  [SL*SEQ*KD];
__device__ __align__(16) bf16 g_Wkmh[BATCH*SEQ*KD], g_Wkml[BATCH*SEQ*KD];
__device__ __align__(16) bf16 g_Sch [SL*SEQ*SEQ], g_Scl[SL*SEQ*SEQ];
__device__ __align__(16) bf16 g_WKth[2*KD*DM], g_WKtl[2*KD*DM];              // WK^T [K][D]
__device__ float g_mask[SL*SEQ];
__device__ float g_part[3*PS];

__device__ __forceinline__ void bsplit(float x, bf16& h, bf16& l)
{
    bf16 hh = __float2bfloat16(x);
    h = hh;
    l = __float2bfloat16(x - __bfloat162float(hh));
}
__device__ __forceinline__ float upk0(uint32_t u){ return __bfloat162float(((__nv_bfloat162*)&u)->x); }
__device__ __forceinline__ float upk1(uint32_t u){ return __bfloat162float(((__nv_bfloat162*)&u)->y); }
__device__ __forceinline__ uint32_t pack2(bf16 a, bf16 b){
    __nv_bfloat162 t; t.x = a; t.y = b; return *(uint32_t*)&t;
}

// ====================== pure-bf16 3-pass tensor-core GEMM ==================
// C = (Ah+Al) @ (Bh+Bl)^T (drop Al*Bl).  A:[M,K], B:[N,K], both row-major.
// Block 128x128, BK=64, 2-stage cp.async, 8 warps (2x4), warp tile 64x32.
// B batch index = blockIdx.z & zband (cross-attn B operands are 16-batch).
// EPI: 0 = fp32 C store; 1 = bias + row-L2 + bf16 split (proj, N=128, grid.x=1)
//      2 = +residual x, emit splits, sumsq partials (self AV)
//      3 = +residual x, emit splits, Sbb/Saa/Sab partials (cross t3)
//      4 = fp32 C store, symmetric (A==B): compute by<=bx, mirror off-diag

__device__ __forceinline__ void mma_bf16(float* c, const uint32_t* a, const uint32_t* b)
{
    asm volatile(
        "mma.sync.aligned.m16n8k16.row.col.f32.bf16.bf16.f32 "
        "{%0,%1,%2,%3},{%4,%5,%6,%7},{%8,%9},{%0,%1,%2,%3};"
        : "+f"(c[0]), "+f"(c[1]), "+f"(c[2]), "+f"(c[3])
        : "r"(a[0]), "r"(a[1]), "r"(a[2]), "r"(a[3]), "r"(b[0]), "r"(b[1]));
}

#define CP_ASYNC16(dst_u32, src_ptr) \
    asm volatile("cp.async.cg.shared.global [%0], [%1], 16;\n" :: "r"(dst_u32), "l"(src_ptr))
#define CP_COMMIT()  asm volatile("cp.async.commit_group;\n" ::)
#define CP_WAIT_1()  asm volatile("cp.async.wait_group 1;\n" ::)
#define CP_WAIT_0()  asm volatile("cp.async.wait_group 0;\n" ::)

// per stage 4 tiles (Ah,Al,Bh,Bl), each [128 rows][36 words] (64 bf16 + 4 pad)
#define ROW_W    36
#define TILE_W   (128*ROW_W)                 // 4608 words
#define STAGE_W  (4*TILE_W)                  // 18432 words
#define GEMM_SMEM_BYTES (2*STAGE_W*4)        // 147456 B (1 CTA/SM; covers mirror)

template<int EPI>
__global__ void __launch_bounds__(256, 1)
k_gemm(const bf16* __restrict__ Ahg, const bf16* __restrict__ Alg,
       const bf16* __restrict__ Bhg, const bf16* __restrict__ Blg,
       float* __restrict__ Cg, bf16* __restrict__ OH, bf16* __restrict__ OL,
       const bf16* __restrict__ RXh, const bf16* __restrict__ RXl,
       const float* __restrict__ bm_aux,   // EPI1: bias[N]; EPI3: mask[b*SEQ]
       float* __restrict__ part, int zband,
       int M, int N, int K, size_t sA, size_t sB, size_t sC)
{
    if (EPI == 4 && blockIdx.y > blockIdx.x) return;   // lower triangle mirrored

    extern __shared__ uint32_t sm[];
    const bf16* Ah = Ahg + (size_t)blockIdx.z * sA;
    const bf16* Al = Alg + (size_t)blockIdx.z * sA;
    const bf16* Bh = Bhg + (size_t)(blockIdx.z & zband) * sB;
    const bf16* Bl = Blg + (size_t)(blockIdx.z & zband) * sB;

    const int bm = blockIdx.y * 128;
    const int bn = blockIdx.x * 128;
    const int tid  = threadIdx.x;
    const int lane = tid & 31;
    const int warp = tid >> 5;
    const int wm = (warp & 1) * 64;
    const int wn = (warp >> 1) * 32;
    const int qid = lane >> 2;
    const int tig = lane & 3;

    const uint32_t sbase = (uint32_t)__cvta_generic_to_shared(sm);

    auto load_stage = [&](int st, int k0) {
        uint32_t stb = sbase + st * (STAGE_W * 4);
        #pragma unroll
        for (int h = 0; h < 4; h++) {
            int idx = tid + h * 256;          // 0..1023
            int rr = idx >> 3, cc = idx & 7;  // row 0..127, 16B chunk 0..7
            uint32_t woff = (rr * ROW_W + cc * 4) * 4;
            size_t ga = (size_t)(bm + rr) * K + k0 + cc * 8;
            size_t gb = (size_t)(bn + rr) * K + k0 + cc * 8;
            CP_ASYNC16(stb + 0*TILE_W*4 + woff, Ah + ga);
            CP_ASYNC16(stb + 1*TILE_W*4 + woff, Al + ga);
            CP_ASYNC16(stb + 2*TILE_W*4 + woff, Bh + gb);
            CP_ASYNC16(stb + 3*TILE_W*4 + woff, Bl + gb);
        }
        CP_COMMIT();
    };

    float acc[4][4][4] = {};
    const int nIter = K >> 6;
    load_stage(0, 0);

    for (int it = 0; it < nIter; ++it) {
        if (it + 1 < nIter) { load_stage((it + 1) & 1, (it + 1) * 64); CP_WAIT_1(); }
        else                { CP_WAIT_0(); }
        __syncthreads();

        const uint32_t* As_h = sm + (it & 1) * STAGE_W;
        const uint32_t* As_l = As_h + TILE_W;
        const uint32_t* Bs_h = As_h + 2*TILE_W;
        const uint32_t* Bs_l = As_h + 3*TILE_W;

        #pragma unroll
        for (int ks = 0; ks < 4; ks++) {
            const int kw = ks * 8 + tig;
            uint32_t ah[4][4], bh[4][2], bl[4][2];
            #pragma unroll
            for (int mi = 0; mi < 4; mi++) {
                int b0 = (wm + mi*16 + qid) * ROW_W + kw;
                ah[mi][0] = As_h[b0];           ah[mi][1] = As_h[b0 + 8*ROW_W];
                ah[mi][2] = As_h[b0 + 4];       ah[mi][3] = As_h[b0 + 8*ROW_W + 4];
            }
            #pragma unroll
            for (int ni = 0; ni < 4; ni++) {
                int b0 = (wn + ni*8 + qid) * ROW_W + kw;
                bh[ni][0] = Bs_h[b0];  bh[ni][1] = Bs_h[b0 + 4];
                bl[ni][0] = Bs_l[b0];  bl[ni][1] = Bs_l[b0 + 4];
            }
            #pragma unroll
            for (int mi = 0; mi < 4; mi++)
                #pragma unroll
                for (int ni = 0; ni < 4; ni++)
                    mma_bf16(acc[mi][ni], ah[mi], bh[ni]);
            #pragma unroll
            for (int mi = 0; mi < 4; mi++)
                #pragma unroll
                for (int ni = 0; ni < 4; ni++)
                    mma_bf16(acc[mi][ni], ah[mi], bl[ni]);
            uint32_t al[4][4];
            #pragma unroll
            for (int mi = 0; mi < 4; mi++) {
                int b0 = (wm + mi*16 + qid) * ROW_W + kw;
                al[mi][0] = As_l[b0];           al[mi][1] = As_l[b0 + 8*ROW_W];
                al[mi][2] = As_l[b0 + 4];       al[mi][3] = As_l[b0 + 8*ROW_W + 4];
            }
            #pragma unroll
            for (int mi = 0; mi < 4; mi++)
                #pragma unroll
                for (int ni = 0; ni < 4; ni++)
                    mma_bf16(acc[mi][ni], al[mi], bh[ni]);
        }
        __syncthreads();
    }

    const size_t zC = (size_t)blockIdx.z * sC;

    if (EPI == 0 || EPI == 4) {
        float* C = Cg + zC;
        #pragma unroll
        for (int mi = 0; mi < 4; mi++)
            #pragma unroll
            for (int ni = 0; ni < 4; ni++) {
                const int r = bm + wm + mi * 16 + qid;
                const int c = bn + wn + ni * 8 + 2 * tig;
                *(float2*)&C[(size_t)r * N + c]       = make_float2(acc[mi][ni][0], acc[mi][ni][1]);
                *(float2*)&C[(size_t)(r + 8) * N + c] = make_float2(acc[mi][ni][2], acc[mi][ni][3]);
            }
        if (EPI == 4 && blockIdx.y != blockIdx.x) {
            float* T = (float*)sm;   // [128][132]
            #pragma unroll
            for (int mi = 0; mi < 4; mi++)
                #pragma unroll
                for (int ni = 0; ni < 4; ni++) {
                    const int rl = wm + mi * 16 + qid;
                    const int cl = wn + ni * 8 + 2 * tig;
                    T[ cl      * 132 + rl]     = acc[mi][ni][0];
                    T[(cl + 1) * 132 + rl]     = acc[mi][ni][1];
                    T[ cl      * 132 + rl + 8] = acc[mi][ni][2];
                    T[(cl + 1) * 132 + rl + 8] = acc[mi][ni][3];
                }
            __syncthreads();
            #pragma unroll 8
            for (int i = 0; i < 64; i++) {
                int lin = tid + i * 256;
                int col = lin >> 7, row = lin & 127;
                C[(size_t)(bn + col) * N + bm + row] = T[col * 132 + row];
            }
        }
    }
    else if (EPI == 1) {
        float* srow = (float*)sm;   // [128][4]
        float rs[4][2];
        #pragma unroll
        for (int mi = 0; mi < 4; mi++) { rs[mi][0] = 0.f; rs[mi][1] = 0.f; }
        #pragma unroll
        for (int mi = 0; mi < 4; mi++)
            #pragma unroll
            for (int ni = 0; ni < 4; ni++) {
                const int c = bn + wn + ni * 8 + 2 * tig;
                float b0 = bm_aux[c], b1 = bm_aux[c + 1];
                acc[mi][ni][0] += b0; acc[mi][ni][1] += b1;
                acc[mi][ni][2] += b0; acc[mi][ni][3] += b1;
                rs[mi][0] += acc[mi][ni][0]*acc[mi][ni][0] + acc[mi][ni][1]*acc[mi][ni][1];
                rs[mi][1] += acc[mi][ni][2]*acc[mi][ni][2] + acc[mi][ni][3]*acc[mi][ni][3];
            }
        #pragma unroll
        for (int mi = 0; mi < 4; mi++)
            #pragma unroll
            for (int h = 0; h < 2; h++) {
                float v = rs[mi][h];
                v += __shfl_xor_sync(0xffffffffu, v, 1);
                v += __shfl_xor_sync(0xffffffffu, v, 2);
                rs[mi][h] = v;
            }
        if (tig == 0)
            #pragma unroll
            for (int mi = 0; mi < 4; mi++)
                #pragma unroll
                for (int h = 0; h < 2; h++)
                    srow[(wm + mi*16 + qid + h*8) * 4 + (wn >> 5)] = rs[mi][h];
        __syncthreads();
        #pragma unroll
        for (int mi = 0; mi < 4; mi++)
            #pragma unroll
            for (int h = 0; h < 2; h++) {
                int rl = wm + mi*16 + qid + h*8;
                float tot = srow[rl*4] + srow[rl*4+1] + srow[rl*4+2] + srow[rl*4+3];
                float inv = 1.f / fmaxf(sqrtf(tot), 1e-12f);
                #pragma unroll
                for (int ni = 0; ni < 4; ni++) {
                    const int c = bn + wn + ni * 8 + 2 * tig;
                    size_t i = zC + (size_t)(bm + rl) * N + c;
                    bf16 h0,l0,h1,l1;
                    bsplit(acc[mi][ni][2*h]   * inv, h0, l0);
                    bsplit(acc[mi][ni][2*h+1] * inv, h1, l1);
                    *(uint32_t*)(OH + i) = pack2(h0, h1);
                    *(uint32_t*)(OL + i) = pack2(l0, l1);
                }
            }
    }
    else {  // EPI 2 / 3: residual add + split emit + partial sums
        const bf16* Xh = RXh + zC;
        const bf16* Xl = RXl + zC;
        float saa = 0.f, sab = 0.f, sbb = 0.f;
        #pragma unroll
        for (int mi = 0; mi < 4; mi++) {
            const int r0 = bm + wm + mi * 16 + qid;
            float mk0 = 0.f, mk1 = 0.f;
            if (EPI == 3) {
                mk0 = bm_aux[blockIdx.z * SEQ + r0];
                mk1 = bm_aux[blockIdx.z * SEQ + r0 + 8];
            }
            #pragma unroll
            for (int ni = 0; ni < 4; ni++) {
                const int c = bn + wn + ni * 8 + 2 * tig;
                size_t i0 = (size_t)r0 * N + c;
                size_t i1 = i0 + (size_t)8 * N;
                uint32_t xh0 = *(const uint32_t*)(Xh + i0), xl0 = *(const uint32_t*)(Xl + i0);
                uint32_t xh1 = *(const uint32_t*)(Xh + i1), xl1 = *(const uint32_t*)(Xl + i1);
                float x00 = upk0(xh0)+upk0(xl0), x01 = upk1(xh0)+upk1(xl0);
                float x10 = upk0(xh1)+upk0(xl1), x11 = upk1(xh1)+upk1(xl1);
                float v00 = acc[mi][ni][0] + x00, v01 = acc[mi][ni][1] + x01;
                float v10 = acc[mi][ni][2] + x10, v11 = acc[mi][ni][3] + x11;
                sbb += v00*v00 + v01*v01 + v10*v10 + v11*v11;
                if (EPI == 3) {
                    float a00 = x00*mk0, a01 = x01*mk0, a10 = x10*mk1, a11 = x11*mk1;
                    saa += a00*a00 + a01*a01 + a10*a10 + a11*a11;
                    sab += a00*v00 + a01*v01 + a10*v10 + a11*v11;
                }
                bf16 h0,l0,h1,l1;
                bsplit(v00, h0, l0); bsplit(v01, h1, l1);
                *(uint32_t*)(OH + zC + i0) = pack2(h0, h1);
                *(uint32_t*)(OL + zC + i0) = pack2(l0, l1);
                bsplit(v10, h0, l0); bsplit(v11, h1, l1);
                *(uint32_t*)(OH + zC + i1) = pack2(h0, h1);
                *(uint32_t*)(OL + zC + i1) = pack2(l0, l1);
            }
        }
        float* red = (float*)sm;   // [3][8]
        #pragma unroll
        for (int o = 16; o; o >>= 1) {
            sbb += __shfl_xor_sync(0xffffffffu, sbb, o);
            if (EPI == 3) {
                saa += __shfl_xor_sync(0xffffffffu, saa, o);
                sab += __shfl_xor_sync(0xffffffffu, sab, o);
            }
        }
        if (lane == 0) {
            red[warp] = sbb;
            if (EPI == 3) { red[8 + warp] = saa; red[16 + warp] = sab; }
        }
        __syncthreads();
        if (tid == 0) {
            const int tileId = blockIdx.y * gridDim.x + blockIdx.x;   // 0..31
            float tb = 0.f; for (int i = 0; i < 8; i++) tb += red[i];
            part[blockIdx.z * 32 + tileId] = tb;
            if (EPI == 3) {
                float ta = 0.f, tc = 0.f;
                for (int i = 0; i < 8; i++) { ta += red[8+i]; tc += red[16+i]; }
                part[PS   + blockIdx.z * 32 + tileId] = ta;   // Saa
                part[2*PS + blockIdx.z * 32 + tileId] = tc;   // Sab
            }
        }
    }
}

// ---------------- weight transpose + split: WK[D][K] -> WKt[K][D] ----------
__global__ void k_split_wt(const float* __restrict__ Wk, bf16* __restrict__ th,
                           bf16* __restrict__ tl)
{
    __shared__ float tile[32][33];
    int k0 = blockIdx.x * 32, d0 = blockIdx.y * 32;
    for (int r = threadIdx.y; r < 32; r += 8)
        tile[r][threadIdx.x] = Wk[(size_t)(d0 + r) * KD + k0 + threadIdx.x];
    __syncthreads();
    for (int r = threadIdx.y; r < 32; r += 8) {
        size_t idx = (size_t)(k0 + r) * DM + d0 + threadIdx.x;
        bsplit(tile[threadIdx.x][r], th[idx], tl[idx]);
    }
}

// ---------------- bulk copy of Xh/Xl slot range (16 batches) ----------------
__global__ void k_copy2(const bf16* __restrict__ sh, const bf16* __restrict__ sl,
                        bf16* __restrict__ dh, bf16* __restrict__ dl)
{
    size_t i = ((size_t)blockIdx.x * 256 + threadIdx.x) * 8;
    *(uint4*)(dh + i) = *(const uint4*)(sh + i);
    *(uint4*)(dl + i) = *(const uint4*)(sl + i);
}

// ---------------- input: [b,D,S] fp32 -> X splits [b,S,D] + Xt [b,D,S] -----
__global__ void k_trans_in(const float* __restrict__ in,
                           bf16* __restrict__ Xh, bf16* __restrict__ Xl,
                           bf16* __restrict__ Xth, bf16* __restrict__ Xtl)
{
    __shared__ bf16 tH[32][33], tL[32][33];
    int b = blockIdx.z;
    int d0 = blockIdx.y * 32, s0 = blockIdx.x * 32;
    for (int r = threadIdx.y; r < 32; r += 8) {
        size_t ti = ((size_t)b*DM + d0 + r) * SEQ + s0 + threadIdx.x;
        bf16 h, l;
        bsplit(in[ti], h, l);
        Xth[ti] = h; Xtl[ti] = l;     // input is already [D][S]
        tH[r][threadIdx.x] = h; tL[r][threadIdx.x] = l;
    }
    __syncthreads();
    for (int r = threadIdx.y; r < 32; r += 8) {
        size_t idx = ((size_t)b*SEQ + s0 + r) * DM + d0 + threadIdx.x;
        Xh[idx] = tH[threadIdx.x][r];
        Xl[idx] = tL[threadIdx.x][r];
    }
}

// ---------------- output transpose: splits [b,S,D] -> fp32 [b,D,S] ---------
__global__ void k_trans_out(const bf16* __restrict__ Xh, const bf16* __restrict__ Xl,
                            float* __restrict__ out)
{
    __shared__ float tile[32][33];
    int b = blockIdx.z;
    int d0 = blockIdx.y * 32, s0 = blockIdx.x * 32;
    for (int r = threadIdx.y; r < 32; r += 8) {
        size_t idx = ((size_t)b*SEQ + s0 + r) * DM + d0 + threadIdx.x;
        tile[r][threadIdx.x] = __bfloat162float(Xh[idx]) + __bfloat162float(Xl[idx]);
    }
    __syncthreads();
    for (int r = threadIdx.y; r < 32; r += 8)
        out[((size_t)b*DM + d0 + r) * SEQ + s0 + threadIdx.x] = tile[threadIdx.x][r];
}

// ---------------- V2^T: (mem * label) transposed + split --------------------
__global__ void k_v2t(const bf16* __restrict__ Mh, const bf16* __restrict__ Ml,
                      const float* __restrict__ lbl,
                      bf16* __restrict__ th, bf16* __restrict__ tl)
{
    __shared__ float tile[32][33];
    int b = blockIdx.z;
    int s0 = blockIdx.x * 32, d0 = blockIdx.y * 32;
    for (int r = threadIdx.y; r < 32; r += 8) {
        size_t idx = ((size_t)b*SEQ + s0 + r) * DM + d0 + threadIdx.x;
        float v = __bfloat162float(Mh[idx]) + __bfloat162float(Ml[idx]);
        tile[r][threadIdx.x] = v * lbl[b*SEQ + s0 + r];
    }
    __syncthreads();
    for (int r = threadIdx.y; r < 32; r += 8) {
        size_t idx = ((size_t)b*DM + d0 + r) * SEQ + s0 + threadIdx.x;
        bsplit(tile[threadIdx.x][r], th[idx], tl[idx]);
    }
}

// ---------------- softmax (optionally fused mask GEMV) ----------------------
template<bool MASK>
__global__ void k_softmax(const float* __restrict__ Sc, bf16* __restrict__ Ph,
                          bf16* __restrict__ Pl, float* __restrict__ mask,
                          const float* __restrict__ lbl, int lband)
{
    __shared__ float sh1[8], sh2[8];
    int b = blockIdx.y, q = blockIdx.x, t = threadIdx.x;   // 256 threads
    size_t ro = ((size_t)b*SEQ + q) * SEQ;
    float4 v = reinterpret_cast<const float4*>(Sc + ro)[t];
    v.x *= TEMP_F; v.y *= TEMP_F; v.z *= TEMP_F; v.w *= TEMP_F;
    float m = fmaxf(fmaxf(v.x, v.y), fmaxf(v.z, v.w));
    #pragma unroll
    for (int o = 16; o; o >>= 1) m = fmaxf(m, __shfl_xor_sync(0xffffffffu, m, o));
    if ((t & 31) == 0) sh1[t >> 5] = m;
    __syncthreads();
    m = fmaxf(fmaxf(fmaxf(sh1[0], sh1[1]), fmaxf(sh1[2], sh1[3])),
              fmaxf(fmaxf(sh1[4], sh1[5]), fmaxf(sh1[6], sh1[7])));
    v.x = __expf(v.x - m); v.y = __expf(v.y - m);
    v.z = __expf(v.z - m); v.w = __expf(v.w - m);
    float sum = v.x + v.y + v.z + v.w;
    #pragma unroll
    for (int o = 16; o; o >>= 1) sum += __shfl_xor_sync(0xffffffffu, sum, o);
    if ((t & 31) == 0) sh2[t >> 5] = sum;
    __syncthreads();
    sum = sh2[0]+sh2[1]+sh2[2]+sh2[3]+sh2[4]+sh2[5]+sh2[6]+sh2[7];
    float inv = 1.f / sum;
    float p0 = v.x*inv, p1 = v.y*inv, p2 = v.z*inv, p3 = v.w*inv;
    bf16 h0,l0,h1,l1,h2,l2,h3,l3;
    bsplit(p0,h0,l0); bsplit(p1,h1,l1); bsplit(p2,h2,l2); bsplit(p3,h3,l3);
    uint2 uh; uh.x = pack2(h0,h1); uh.y = pack2(h2,h3);
    uint2 ul; ul.x = pack2(l0,l1); ul.y = pack2(l2,l3);
    *(uint2*)(Ph + ro + 4*t) = uh;
    *(uint2*)(Pl + ro + 4*t) = ul;
    if (MASK) {
        float4 L = reinterpret_cast<const float4*>(lbl + (size_t)(b & lband)*SEQ)[t];
        float s = p0*L.x + p1*L.y + p2*L.z + p3*L.w;
        #pragma unroll
        for (int o = 16; o; o >>= 1) s += __shfl_xor_sync(0xffffffffu, s, o);
        __syncthreads();
        if ((t & 31) == 0) sh1[t >> 5] = s;
        __syncthreads();
        if (t == 0)
            mask[b*SEQ + q] = sh1[0]+sh1[1]+sh1[2]+sh1[3]+sh1[4]+sh1[5]+sh1[6]+sh1[7];
    }
}

// ---------------- self-norm finalize: linear (no Xt emit) -------------------
__global__ void k_scale_emit8(const bf16* __restrict__ Bh, const bf16* __restrict__ Bl,
                              const float* __restrict__ part,
                              bf16* __restrict__ Xh, bf16* __restrict__ Xl)
{
    int b = blockIdx.y;
    float s = 0.f;
    #pragma unroll
    for (int i = 0; i < 32; i++) s += part[b*32 + i];
    float f = NORM_SCALE_F * sqrtf(524288.f / (s + 1e-5f));
    size_t i = (size_t)b*EPB + (size_t)blockIdx.x*2048 + threadIdx.x*8;
    uint4 uh = *(const uint4*)(Bh + i);
    uint4 ul = *(const uint4*)(Bl + i);
    uint32_t oh[4], ol[4];
    const uint32_t* ph = (const uint32_t*)&uh;
    const uint32_t* pl = (const uint32_t*)&ul;
    #pragma unroll
    for (int j = 0; j < 4; j++) {
        float v0 = (upk0(ph[j]) + upk0(pl[j])) * f;
        float v1 = (upk1(ph[j]) + upk1(pl[j])) * f;
        bf16 h0,l0,h1,l1;
        bsplit(v0,h0,l0); bsplit(v1,h1,l1);
        oh[j] = pack2(h0,h1); ol[j] = pack2(l0,l1);
    }
    *(uint4*)(Xh + i) = *(uint4*)oh;
    *(uint4*)(Xl + i) = *(uint4*)ol;
}

// ---------------- self-norm finalize: tiled, emits Xt too -------------------
__global__ void k_scale_emit_tr(const bf16* __restrict__ Bh, const bf16* __restrict__ Bl,
                                const float* __restrict__ part,
                                bf16* __restrict__ Xh, bf16* __restrict__ Xl,
                                bf16* __restrict__ Xth, bf16* __restrict__ Xtl)
{
    __shared__ bf16 tH[32][33], tL[32][33];
    int b = blockIdx.z;
    float s = 0.f;
    #pragma unroll
    for (int i = 0; i < 32; i++) s += part[b*32 + i];
    float f = NORM_SCALE_F * sqrtf(524288.f / (s + 1e-5f));
    int s0 = blockIdx.x * 32, d0 = blockIdx.y * 32;
    for (int r = threadIdx.y; r < 32; r += 8) {
        size_t idx = ((size_t)b*SEQ + s0 + r) * DM + d0 + threadIdx.x;
        float v = (__bfloat162float(Bh[idx]) + __bfloat162float(Bl[idx])) * f;
        bf16 h, l; bsplit(v, h, l);
        Xh[idx] = h; Xl[idx] = l;
        tH[r][threadIdx.x] = h; tL[r][threadIdx.x] = l;
    }
    __syncthreads();
    for (int r = threadIdx.y; r < 32; r += 8) {
        size_t idx = ((size_t)b*DM + d0 + r) * SEQ + s0 + threadIdx.x;
        Xth[idx] = tH[threadIdx.x][r];
        Xtl[idx] = tL[threadIdx.x][r];
    }
}

// ---------------- cross finalize: tiled, factors inline, emits Xt -----------
__global__ void k_cross_final_tr(bf16* __restrict__ Xh, bf16* __restrict__ Xl,
                                 const bf16* __restrict__ Bh, const bf16* __restrict__ Bl,
                                 const float* __restrict__ mask,
                                 const float* __restrict__ part,
                                 bf16* __restrict__ Xth, bf16* __restrict__ Xtl)
{
    __shared__ bf16 tH[32][33], tL[32][33];
    int b = blockIdx.z;
    float sbb = 0.f, saa = 0.f, sab = 0.f;
    #pragma unroll
    for (int i = 0; i < 32; i++) {
        sbb += part[b*32 + i];
        saa += part[PS   + b*32 + i];
        sab += part[2*PS + b*32 + i];
    }
    float f2 = NORM_SCALE_F * sqrtf(524288.f / (saa + 1e-5f));
    float f4 = NORM_SCALE_F * sqrtf(524288.f / (sbb + 1e-5f));
    float sf = f2*f2*saa + 2.f*f2*f4*sab + f4*f4*sbb;
    float F  = NORM_SCALE_F * sqrtf(524288.f / (sf + 1e-5f));
    float ca = F * f2, cb = F * f4;

    int s0 = blockIdx.x * 32, d0 = blockIdx.y * 32;
    for (int r = threadIdx.y; r < 32; r += 8) {
        size_t idx = ((size_t)b*SEQ + s0 + r) * DM + d0 + threadIdx.x;
        float camk = ca * mask[b*SEQ + s0 + r];
        float x = __bfloat162float(Xh[idx]) + __bfloat162float(Xl[idx]);
        float bv = __bfloat162float(Bh[idx]) + __bfloat162float(Bl[idx]);
        float v = camk * x + cb * bv;
        bf16 h, l; bsplit(v, h, l);
        Xh[idx] = h; Xl[idx] = l;
        tH[r][threadIdx.x] = h; tL[r][threadIdx.x] = l;
    }
    __syncthreads();
    for (int r = threadIdx.y; r < 32; r += 8) {
        size_t idx = ((size_t)b*DM + d0 + r) * SEQ + s0 + threadIdx.x;
        Xth[idx] = tH[threadIdx.x][r];
        Xtl[idx] = tL[threadIdx.x][r];
    }
}

// =================== host-side orchestration ===============================
namespace {

struct Ptrs {
    float *Sc, *mask, *part;
    bf16 *Xh, *Xl, *Xth, *Xtl, *V2th, *V2tl, *Bh, *Bl,
         *Wh, *Wl, *Wkmh, *Wkml, *Sch, *Scl, *WKth, *WKtl;
};

// zoff = batch-slot offset for X/W/Sc-family pointers (mask/part stay z-indexed)
inline void proj(int wsel, const float* bK, bf16* outH, bf16* outL,
                 int nb, int zoff, const Ptrs& p)
{
    k_gemm<1><<<dim3(1, 8, nb), 256, GEMM_SMEM_BYTES>>>(
        p.Xh + (size_t)zoff*EPB, p.Xl + (size_t)zoff*EPB,
        p.WKth + (size_t)wsel*KD*DM, p.WKtl + (size_t)wsel*KD*DM,
        nullptr, outH + (size_t)zoff*SEQ*KD, outL + (size_t)zoff*SEQ*KD,
        nullptr, nullptr, bK, nullptr, 0,
        SEQ, KD, DM, (size_t)SEQ*DM, 0, (size_t)SEQ*KD);
}

inline void self_block(const float* bKs, bool emitT, int nb, int zoff, const Ptrs& p)
{
    const size_t xo = (size_t)zoff*EPB, wo = (size_t)zoff*SEQ*KD,
                 so = (size_t)zoff*SEQ*SEQ;
    proj(0, bKs, p.Wh, p.Wl, nb, zoff, p);
    k_gemm<4><<<dim3(8, 8, nb), 256, GEMM_SMEM_BYTES>>>(     // symmetric scores
        p.Wh + wo, p.Wl + wo, p.Wh + wo, p.Wl + wo, p.Sc + so,
        nullptr, nullptr, nullptr, nullptr, nullptr, nullptr, 63,
        SEQ, SEQ, KD, (size_t)SEQ*KD, (size_t)SEQ*KD, (size_t)SEQ*SEQ);
    k_softmax<false><<<dim3(SEQ, nb), 256>>>(p.Sc + so, p.Sch + so, p.Scl + so,
                                             nullptr, nullptr, 0);
    k_gemm<2><<<dim3(4, 8, nb), 256, GEMM_SMEM_BYTES>>>(
        p.Sch + so, p.Scl + so, p.Xth + xo, p.Xtl + xo, nullptr,
        p.Bh + xo, p.Bl + xo, p.Xh + xo, p.Xl + xo,
        nullptr, p.part, 63, SEQ, DM, SEQ,
        (size_t)SEQ*SEQ, (size_t)DM*SEQ, (size_t)SEQ*DM);
    if (emitT)
        k_scale_emit_tr<<<dim3(32, 16, nb), dim3(32, 8)>>>(
            p.Bh + xo, p.Bl + xo, p.part, p.Xh + xo, p.Xl + xo,
            p.Xth + xo, p.Xtl + xo);
    else
        k_scale_emit8<<<dim3(256, nb), 256>>>(p.Bh + xo, p.Bl + xo, p.part,
                                              p.Xh + xo, p.Xl + xo);
}

// cross: B-operands Wkm/V2t and labels are 16-batch (band 15)
inline void cross_block(const float* bKc, const float* lbl, int nb, int zoff,
                        const Ptrs& p)
{
    const size_t xo = (size_t)zoff*EPB, wo = (size_t)zoff*SEQ*KD,
                 so = (size_t)zoff*SEQ*SEQ;
    proj(1, bKc, p.Wh, p.Wl, nb, zoff, p);
    k_gemm<0><<<dim3(8, 8, nb), 256, GEMM_SMEM_BYTES>>>(
        p.Wh + wo, p.Wl + wo, p.Wkmh, p.Wkml, p.Sc + so,
        nullptr, nullptr, nullptr, nullptr, nullptr, nullptr, 15,
        SEQ, SEQ, KD, (size_t)SEQ*KD, (size_t)SEQ*KD, (size_t)SEQ*SEQ);
    k_softmax<true><<<dim3(SEQ, nb), 256>>>(p.Sc + so, p.Sch + so, p.Scl + so,
                                            p.mask, lbl, 15);
    k_gemm<3><<<dim3(4, 8, nb), 256, GEMM_SMEM_BYTES>>>(
        p.Sch + so, p.Scl + so, p.V2th, p.V2tl, nullptr,
        p.Bh + xo, p.Bl + xo, p.Xh + xo, p.Xl + xo,
        p.mask, p.part, 15, SEQ, DM, SEQ,
        (size_t)SEQ*SEQ, (size_t)DM*SEQ, (size_t)SEQ*DM);
    k_cross_final_tr<<<dim3(32, 16, nb), dim3(32, 8)>>>(
        p.Xh + xo, p.Xl + xo, p.Bh + xo, p.Bl + xo, p.mask, p.part,
        p.Xth + xo, p.Xtl + xo);
}

} // namespace

extern "C" void kernel_launch(void* const* d_in, const int* in_sizes, int n_in,
                              void* d_out, int out_size)
{
    const float* train = (const float*)d_in[0];
    const float* test  = (const float*)d_in[1];
    const float* lbl   = (const float*)d_in[2];
    const float* WKs   = (const float*)d_in[3];
    const float* bKs   = (const float*)d_in[4];
    const float* WKc   = (const float*)d_in[5];
    const float* bKc   = (const float*)d_in[6];
    float* out = (float*)d_out;

    cudaFuncSetAttribute(k_gemm<0>, cudaFuncAttributeMaxDynamicSharedMemorySize, GEMM_SMEM_BYTES);
    cudaFuncSetAttribute(k_gemm<1>, cudaFuncAttributeMaxDynamicSharedMemorySize, GEMM_SMEM_BYTES);
    cudaFuncSetAttribute(k_gemm<2>, cudaFuncAttributeMaxDynamicSharedMemorySize, GEMM_SMEM_BYTES);
    cudaFuncSetAttribute(k_gemm<3>, cudaFuncAttributeMaxDynamicSharedMemorySize, GEMM_SMEM_BYTES);
    cudaFuncSetAttribute(k_gemm<4>, cudaFuncAttributeMaxDynamicSharedMemorySize, GEMM_SMEM_BYTES);

    Ptrs p;
    cudaGetSymbolAddress((void**)&p.Sc,   g_Sc);
    cudaGetSymbolAddress((void**)&p.mask, g_mask);
    cudaGetSymbolAddress((void**)&p.part, g_part);
    cudaGetSymbolAddress((void**)&p.Xh,   g_Xh);
    cudaGetSymbolAddress((void**)&p.Xl,   g_Xl);
    cudaGetSymbolAddress((void**)&p.Xth,  g_Xth);
    cudaGetSymbolAddress((void**)&p.Xtl,  g_Xtl);
    cudaGetSymbolAddress((void**)&p.V2th, g_V2th);
    cudaGetSymbolAddress((void**)&p.V2tl, g_V2tl);
    cudaGetSymbolAddress((void**)&p.Bh,   g_Bh);
    cudaGetSymbolAddress((void**)&p.Bl,   g_Bl);
    cudaGetSymbolAddress((void**)&p.Wh,   g_Wh);
    cudaGetSymbolAddress((void**)&p.Wl,   g_Wl);
    cudaGetSymbolAddress((void**)&p.Wkmh, g_Wkmh);
    cudaGetSymbolAddress((void**)&p.Wkml, g_Wkml);
    cudaGetSymbolAddress((void**)&p.Sch,  g_Sch);
    cudaGetSymbolAddress((void**)&p.Scl,  g_Scl);
    cudaGetSymbolAddress((void**)&p.WKth, g_WKth);
    cudaGetSymbolAddress((void**)&p.WKtl, g_WKtl);

    // weight transpose + split
    k_split_wt<<<dim3(4, 16), dim3(32, 8)>>>(WKs, p.WKth,         p.WKtl);
    k_split_wt<<<dim3(4, 16), dim3(32, 8)>>>(WKc, p.WKth + KD*DM, p.WKtl + KD*DM);

    const size_t ho1 = (size_t)16 * EPB;   // slot-16 offset in X-family tensors

    // ---- shared layer-1 self block (= encoder L1 = train-decoder L1 self) ----
    k_trans_in<<<dim3(32, 16, BATCH), dim3(32, 8)>>>(train, p.Xh, p.Xl, p.Xth, p.Xtl);
    self_block(bKs, true, BATCH, 0, p);                    // slots 0..15, emits Xt

    // stash L1 output X into train-decoder slots 16..31 (Xt regenerated later)
    k_copy2<<<4096, 256>>>(p.Xh, p.Xl, p.Xh + ho1, p.Xl + ho1);

    // ---- encoder layer-2 (slots 0..15 -> memory) ----
    self_block(bKs, false, BATCH, 0, p);

    // cross-attn invariants from memory
    proj(1, bKc, p.Wkmh, p.Wkml, BATCH, 0, p);             // wk(memory), wo=0 ok (Wkm unshifted)
    k_v2t<<<dim3(32, 16, BATCH), dim3(32, 8)>>>(p.Xh, p.Xl, lbl, p.V2th, p.V2tl);

    // ---- test decoder input + its layer-1 self (slots 32..47) ----
    k_trans_in<<<dim3(32, 16, BATCH), dim3(32, 8)>>>(test, p.Xh + 2*ho1, p.Xl + 2*ho1,
                                                          p.Xth + 2*ho1, p.Xtl + 2*ho1);
    self_block(bKs, false, BATCH, 32, p);

    // ---- joint decoders (32 batches, slots 16..47): L1 cross, L2 self, L2 cross
    cross_block(bKc, lbl, 32, 16, p);
    self_block(bKs, false, 32, 16, p);
    cross_block(bKc, lbl, 32, 16, p);

    // out is [2,B,D,H,W] = [train 16][test 16] = slots 16..47
    k_trans_out<<<dim3(32, 16, 32), dim3(32, 8)>>>(p.Xh + ho1, p.Xl + ho1, out);
}